// round 3
// baseline (speedup 1.0000x reference)
#include <cuda_runtime.h>
#include <math.h>

#define NN 50000
#define NE 800000
#define NG 500
#define CC 64
#define NL 13          // 1 + 12 PDN convs
#define LSTRIDE 292    // per-layer smem stride for edge MLP weights

// modes for k_agg epilogue
#define M_COPY  1
#define M_SKIP  2
#define M_STATS 4
#define M_POOL  8

// ---------------- scratch (device globals; no allocation) ----------------
__device__ float  g_h  [NN*CC];
__device__ float  g_cur[NN*CC];
__device__ float  g_acc[NN*CC];
__device__ float  g_ew [NL*NE];     // raw ew (CSR order) -> scaled to norm in k_norm
__device__ float  g_deg[NN*16];     // [node][16] deg -> rsqrt(deg) in place
__device__ int    g_cnt[NN];
__device__ int    g_rowptr[NN+1];
__device__ int    g_cursor[NN];
__device__ int    g_eid [NE];
__device__ int    g_csrc[NE];
__device__ int    g_cdst[NE];
__device__ double g_colsum[13*64];
__device__ double g_colsq [13*64];
__device__ float  g_pool[NG*CC];

// ---------------- init ----------------
__global__ void k_reset() {
    int i = blockIdx.x*blockDim.x + threadIdx.x;
    if (i < NN*16) g_deg[i] = 1.0f;          // deg starts at self-loop weight 1
    if (i < NN)    g_cnt[i] = 0;
    if (i < NG*CC) g_pool[i] = 0.0f;
    if (i < 13*64) { g_colsum[i] = 0.0; g_colsq[i] = 0.0; }
}

// ---------------- CSR build ----------------
__global__ void k_hist(const int* __restrict__ dst) {
    int e = blockIdx.x*blockDim.x + threadIdx.x;
    if (e < NE) atomicAdd(&g_cnt[dst[e]], 1);
}

// single-block chunked scan: 1024 threads, 49 chunks
__global__ void k_scanall() {
    __shared__ int wsum[32];
    int t = threadIdx.x;
    int lane = t & 31, wid = t >> 5;
    int carry = 0;
    for (int base = 0; base < NN; base += 1024) {
        int i = base + t;
        int v = (i < NN) ? g_cnt[i] : 0;
        int x = v;
        #pragma unroll
        for (int off = 1; off < 32; off <<= 1) {
            int u = __shfl_up_sync(0xffffffffu, x, off);
            if (lane >= off) x += u;
        }
        if (lane == 31) wsum[wid] = x;
        __syncthreads();
        if (wid == 0) {
            int y = wsum[lane];
            #pragma unroll
            for (int off = 1; off < 32; off <<= 1) {
                int u = __shfl_up_sync(0xffffffffu, y, off);
                if (lane >= off) y += u;
            }
            wsum[lane] = y;
        }
        __syncthreads();
        int pre = (wid > 0) ? wsum[wid-1] : 0;
        int excl = carry + pre + x - v;
        if (i < NN) { g_rowptr[i] = excl; g_cursor[i] = excl; }
        int tot = wsum[31];
        __syncthreads();
        carry += tot;
    }
    if (t == 0) g_rowptr[NN] = carry;
}

__global__ void k_scatter(const int* __restrict__ src, const int* __restrict__ dst) {
    int e = blockIdx.x*blockDim.x + threadIdx.x;
    if (e >= NE) return;
    int d = dst[e];
    int p = atomicAdd(&g_cursor[d], 1);
    g_eid[p]  = e;
    g_csrc[p] = src[e];
    g_cdst[p] = d;
}

// ---------------- edge MLPs: all 13 layers in one pass (NE exactly divisible by 256) ----------------
__global__ __launch_bounds__(256) void k_edgemlp(
    const float* __restrict__ ea,
    const float* __restrict__ m1W, const float* __restrict__ m1b,
    const float* __restrict__ m2W, const float* __restrict__ m2b,
    const float* __restrict__ hm1W, const float* __restrict__ hm1b,
    const float* __restrict__ hm2W, const float* __restrict__ hm2b)
{
    __shared__ __align__(16) float sw[NL*LSTRIDE];
    for (int idx = threadIdx.x; idx < NL*LSTRIDE; idx += 256) {
        int l = idx / LSTRIDE, r = idx - l*LSTRIDE;
        float v = 0.0f;
        if (r < 256) {
            int j = r >> 4, i = r & 15;
            v = (l == 0) ? m1W[i*16 + j] : hm1W[(l-1)*256 + i*16 + j];
        } else if (r < 272) {
            v = (l == 0) ? m1b[r-256] : hm1b[(l-1)*16 + (r-256)];
        } else if (r < 288) {
            v = (l == 0) ? m2W[r-272] : hm2W[(l-1)*16 + (r-272)];
        } else if (r == 288) {
            v = (l == 0) ? m2b[0] : hm2b[l-1];
        }
        sw[idx] = v;
    }
    __syncthreads();

    const unsigned FULL = 0xffffffffu;
    int p = blockIdx.x*256 + threadIdx.x;   // always < NE
    int lane = threadIdx.x & 31;
    int e = g_eid[p];
    int d = g_cdst[p];

    // segment structure within warp (d runs are contiguous in CSR order)
    int dprev = __shfl_up_sync(FULL, d, 1);
    bool head = (lane == 0) || (dprev != d);
    unsigned hmask = __ballot_sync(FULL, head);
    unsigned below = hmask & ((2u << lane) - 1u);
    int hd = 31 - __clz(below);
    bool lastl = (lane == 31) || ((hmask >> (lane+1)) & 1u);

    float a[16];
    const float4* ap = (const float4*)(ea + e*16);
    #pragma unroll
    for (int q = 0; q < 4; q++) {
        float4 v = ap[q];
        a[4*q+0]=v.x; a[4*q+1]=v.y; a[4*q+2]=v.z; a[4*q+3]=v.w;
    }

    #pragma unroll 1
    for (int l = 0; l < NL; l++) {
        const float* W = &sw[l*LSTRIDE];
        float z = W[288];
        #pragma unroll
        for (int j = 0; j < 16; j++) {
            const float4* wc = (const float4*)&W[j*16];
            float4 w0 = wc[0], w1 = wc[1], w2 = wc[2], w3 = wc[3];
            float t = W[256+j];
            t=fmaf(a[0],w0.x,t); t=fmaf(a[1],w0.y,t); t=fmaf(a[2],w0.z,t); t=fmaf(a[3],w0.w,t);
            t=fmaf(a[4],w1.x,t); t=fmaf(a[5],w1.y,t); t=fmaf(a[6],w1.z,t); t=fmaf(a[7],w1.w,t);
            t=fmaf(a[8],w2.x,t); t=fmaf(a[9],w2.y,t); t=fmaf(a[10],w2.z,t); t=fmaf(a[11],w2.w,t);
            t=fmaf(a[12],w3.x,t); t=fmaf(a[13],w3.y,t); t=fmaf(a[14],w3.z,t); t=fmaf(a[15],w3.w,t);
            t = fmaxf(t, 0.0f);
            z = fmaf(t, W[272+j], z);
        }
        float ew = 1.0f / (1.0f + __expf(-z));
        g_ew[l*NE + p] = ew;

        // warp-segmented sum -> one atomic per (warp, dst-run)
        float v = ew;
        #pragma unroll
        for (int off = 1; off < 32; off <<= 1) {
            float u = __shfl_up_sync(FULL, v, off);
            if (lane - off >= hd) v += u;
        }
        if (lastl) atomicAdd(&g_deg[d*16 + l], v);
    }
}

__global__ void k_rsqrt() {
    int i = blockIdx.x*blockDim.x + threadIdx.x;
    if (i < NN*16) g_deg[i] = rsqrtf(g_deg[i]);   // deg >= 1 always
}

__global__ void k_norm() {
    int p = blockIdx.x*256 + threadIdx.x;   // always < NE
    int s = g_csrc[p], d = g_cdst[p];
    float ds[16], dd[16];
    const float4* sp = (const float4*)(g_deg + s*16);
    const float4* dp = (const float4*)(g_deg + d*16);
    #pragma unroll
    for (int q = 0; q < 4; q++) {
        float4 v = sp[q]; ds[4*q]=v.x; ds[4*q+1]=v.y; ds[4*q+2]=v.z; ds[4*q+3]=v.w;
        float4 u = dp[q]; dd[4*q]=u.x; dd[4*q+1]=u.y; dd[4*q+2]=u.z; dd[4*q+3]=u.w;
    }
    #pragma unroll
    for (int l = 0; l < NL; l++)
        g_ew[l*NE + p] *= ds[l]*dd[l];
}

// ---------------- fused BN+ReLU+GEMM, 2 rows/thread ----------------
#define GSTEP2(A0V, A1V, KIDX) {                                      \
    const float4* wr = (const float4*)&sW[(KIDX)*64];                 \
    _Pragma("unroll")                                                 \
    for (int j = 0; j < 16; j++) {                                    \
        float4 w = wr[j];                                             \
        acc0[4*j+0] = fmaf((A0V), w.x, acc0[4*j+0]);                  \
        acc0[4*j+1] = fmaf((A0V), w.y, acc0[4*j+1]);                  \
        acc0[4*j+2] = fmaf((A0V), w.z, acc0[4*j+2]);                  \
        acc0[4*j+3] = fmaf((A0V), w.w, acc0[4*j+3]);                  \
        acc1[4*j+0] = fmaf((A1V), w.x, acc1[4*j+0]);                  \
        acc1[4*j+1] = fmaf((A1V), w.y, acc1[4*j+1]);                  \
        acc1[4*j+2] = fmaf((A1V), w.z, acc1[4*j+2]);                  \
        acc1[4*j+3] = fmaf((A1V), w.w, acc1[4*j+3]);                  \
    } }

__global__ __launch_bounds__(128) void k_gemm(
    const float* __restrict__ A, const float* __restrict__ W,
    float* __restrict__ H, int slot)     // slot < 0 : no BN
{
    __shared__ __align__(16) float sW[64*64];
    __shared__ float smu[64], ssc[64];
    int t = threadIdx.x;
    const float4* W4 = (const float4*)W;
    float4* sW4 = (float4*)sW;
    #pragma unroll
    for (int i = 0; i < 8; i++) sW4[t + i*128] = W4[t + i*128];
    if (slot >= 0 && t < 64) {
        double mu  = g_colsum[slot*64 + t] / (double)NN;
        double var = g_colsq[slot*64 + t] / (double)NN - mu*mu;
        if (var < 0.0) var = 0.0;
        smu[t] = (float)mu;
        ssc[t] = (float)(1.0 / sqrt(var + 1e-5));
    }
    __syncthreads();

    int r0 = blockIdx.x*256 + t;
    int r1 = r0 + 128;
    bool v1 = (r1 < NN);
    if (r0 >= NN) return;
    const float4* A0 = (const float4*)(A + r0*64);
    const float4* A1 = (const float4*)(A + (v1 ? r1 : r0)*64);

    float acc0[64], acc1[64];
    #pragma unroll
    for (int j = 0; j < 64; j++) { acc0[j] = 0.0f; acc1[j] = 0.0f; }

    #pragma unroll 1
    for (int g = 0; g < 16; g++) {
        float4 a0 = A0[g];
        float4 a1 = A1[g];
        if (slot >= 0) {
            a0.x = fmaxf((a0.x - smu[4*g+0]) * ssc[4*g+0], 0.0f);
            a0.y = fmaxf((a0.y - smu[4*g+1]) * ssc[4*g+1], 0.0f);
            a0.z = fmaxf((a0.z - smu[4*g+2]) * ssc[4*g+2], 0.0f);
            a0.w = fmaxf((a0.w - smu[4*g+3]) * ssc[4*g+3], 0.0f);
            a1.x = fmaxf((a1.x - smu[4*g+0]) * ssc[4*g+0], 0.0f);
            a1.y = fmaxf((a1.y - smu[4*g+1]) * ssc[4*g+1], 0.0f);
            a1.z = fmaxf((a1.z - smu[4*g+2]) * ssc[4*g+2], 0.0f);
            a1.w = fmaxf((a1.w - smu[4*g+3]) * ssc[4*g+3], 0.0f);
        }
        GSTEP2(a0.x, a1.x, 4*g+0);
        GSTEP2(a0.y, a1.y, 4*g+1);
        GSTEP2(a0.z, a1.z, 4*g+2);
        GSTEP2(a0.w, a1.w, 4*g+3);
    }
    float4* H0 = (float4*)(H + r0*64);
    #pragma unroll
    for (int j = 0; j < 16; j++) {
        float4 o; o.x=acc0[4*j]; o.y=acc0[4*j+1]; o.z=acc0[4*j+2]; o.w=acc0[4*j+3];
        H0[j] = o;
    }
    if (v1) {
        float4* H1 = (float4*)(H + r1*64);
        #pragma unroll
        for (int j = 0; j < 16; j++) {
            float4 o; o.x=acc1[4*j]; o.y=acc1[4*j+1]; o.z=acc1[4*j+2]; o.w=acc1[4*j+3];
            H1[j] = o;
        }
    }
}

// ---------------- CSR aggregation + fused epilogues ----------------
// out[d] = sum norm*h[src] + dis^2*h[d] + bias ; then optional skip / acc-copy / BN stats / pool
__global__ __launch_bounds__(256) void k_agg(
    const float* __restrict__ h, const float* __restrict__ nrm,
    int layer, const float* __restrict__ bias,
    float* __restrict__ cur, float* __restrict__ acc,
    const int* __restrict__ batch, int mode, int slot)
{
    __shared__ float2 sred[256];
    int t = threadIdx.x;
    int w = (blockIdx.x*256 + t) >> 5;
    int lane = t & 31;
    int c = lane*2;
    float ax = 0.0f, ay = 0.0f;
    if (w < NN) {
        float dv = g_deg[w*16 + layer];
        float selfw = dv*dv;
        float2 hv = *(const float2*)(h + w*64 + c);
        ax = fmaf(selfw, hv.x, bias[c]);
        ay = fmaf(selfw, hv.y, bias[c+1]);
        int p0 = g_rowptr[w], p1 = g_rowptr[w+1];
        int p = p0;
        for (; p + 3 < p1; p += 4) {
            int s0 = g_csrc[p],   s1 = g_csrc[p+1];
            int s2 = g_csrc[p+2], s3 = g_csrc[p+3];
            float w0 = nrm[p],   w1 = nrm[p+1];
            float w2 = nrm[p+2], w3 = nrm[p+3];
            float2 v0 = *(const float2*)(h + s0*64 + c);
            float2 v1v = *(const float2*)(h + s1*64 + c);
            float2 v2 = *(const float2*)(h + s2*64 + c);
            float2 v3 = *(const float2*)(h + s3*64 + c);
            ax = fmaf(w0, v0.x, ax);  ay = fmaf(w0, v0.y, ay);
            ax = fmaf(w1, v1v.x, ax); ay = fmaf(w1, v1v.y, ay);
            ax = fmaf(w2, v2.x, ax);  ay = fmaf(w2, v2.y, ay);
            ax = fmaf(w3, v3.x, ax);  ay = fmaf(w3, v3.y, ay);
        }
        for (; p < p1; p++) {
            int s = g_csrc[p];
            float wt = nrm[p];
            float2 v = *(const float2*)(h + s*64 + c);
            ax = fmaf(wt, v.x, ax);
            ay = fmaf(wt, v.y, ay);
        }
        if (mode & M_SKIP) {
            float2 a2 = *(float2*)(acc + w*64 + c);
            ax += a2.x; ay += a2.y;
            a2.x += ax; a2.y += ay;
            *(float2*)(acc + w*64 + c) = a2;
        }
        float2 o; o.x = ax; o.y = ay;
        *(float2*)(cur + w*64 + c) = o;
        if (mode & M_COPY) *(float2*)(acc + w*64 + c) = o;
        if (mode & M_POOL) {
            float rx = fmaxf(ax, 0.0f), ry = fmaxf(ay, 0.0f);
            int b = batch[w];
            atomicMax((int*)&g_pool[b*64 + c],     __float_as_int(rx));
            atomicMax((int*)&g_pool[b*64 + c + 1], __float_as_int(ry));
        }
    }
    if (mode & M_STATS) {
        float2 sv; sv.x = ax; sv.y = ay;
        sred[t] = sv;
        __syncthreads();
        if (t < 64) {
            int ln = t >> 1, par = t & 1;
            double S = 0.0, Q = 0.0;
            #pragma unroll
            for (int wi = 0; wi < 8; wi++) {
                float2 v2 = sred[wi*32 + ln];
                float v = par ? v2.y : v2.x;
                S += v; Q += (double)v*v;
            }
            atomicAdd(&g_colsum[slot*64 + t], S);
            atomicAdd(&g_colsq [slot*64 + t], Q);
        }
    }
}

// ---------------- readout ----------------
__global__ void k_final(const float* __restrict__ linW, const float* __restrict__ linb,
                        float* __restrict__ out) {
    int g = blockIdx.x*blockDim.x + threadIdx.x;
    if (g >= NG) return;
    float a0 = linb[0], a1 = linb[1];
    #pragma unroll 8
    for (int c = 0; c < CC; c++) {
        float v = g_pool[g*64 + c];
        a0 = fmaf(v, linW[c*2+0], a0);
        a1 = fmaf(v, linW[c*2+1], a1);
    }
    out[g*2+0] = a0;
    out[g*2+1] = a1;
}

// ---------------- launch ----------------
extern "C" void kernel_launch(void* const* d_in, const int* in_sizes, int n_in,
                              void* d_out, int out_size)
{
    const float* x     = (const float*)d_in[0];
    const int*   ei    = (const int*)  d_in[1];
    const int*   batch = (const int*)  d_in[2];
    /* d_in[3] = dropout (unused, eval mode) */
    const float* ea    = (const float*)d_in[4];
    const float* Wlin1 = (const float*)d_in[5];
    const float* bias1 = (const float*)d_in[6];
    const float* m1W1  = (const float*)d_in[7];
    const float* m1b1  = (const float*)d_in[8];
    const float* m2W1  = (const float*)d_in[9];
    const float* m2b1  = (const float*)d_in[10];
    const float* hWlin = (const float*)d_in[11];
    const float* hbias = (const float*)d_in[12];
    const float* hm1W  = (const float*)d_in[13];
    const float* hm1b  = (const float*)d_in[14];
    const float* hm2W  = (const float*)d_in[15];
    const float* hm2b  = (const float*)d_in[16];
    const float* linW  = (const float*)d_in[17];
    const float* linb  = (const float*)d_in[18];
    float* out = (float*)d_out;

    const int* src = ei;
    const int* dst = ei + NE;

    float *p_h, *p_cur, *p_acc, *p_ew;
    cudaGetSymbolAddress((void**)&p_h,   g_h);
    cudaGetSymbolAddress((void**)&p_cur, g_cur);
    cudaGetSymbolAddress((void**)&p_acc, g_acc);
    cudaGetSymbolAddress((void**)&p_ew,  g_ew);

    const int EB = NE / 256;                  // 3125 (exact)
    const int GB = (NN + 255) / 256;          // 196 blocks x 256 rows
    const int AB = (NN*32) / 256;             // 6250 (exact)

    // prologue: CSR + all edge norms for all 13 layers
    k_reset  <<<(NN*16 + 255)/256, 256>>>();
    k_hist   <<<EB, 256>>>(dst);
    k_scanall<<<1, 1024>>>();
    k_scatter<<<EB, 256>>>(src, dst);
    k_edgemlp<<<EB, 256>>>(ea, m1W1, m1b1, m2W1, m2b1, hm1W, hm1b, hm2W, hm2b);
    k_rsqrt  <<<(NN*16 + 255)/256, 256>>>();
    k_norm   <<<EB, 256>>>();

    // conv1: gemm (no BN) + agg (copy acc, stats for hidden layer 0)
    k_gemm<<<GB, 128>>>(x, Wlin1, p_h, -1);
    k_agg <<<AB, 256>>>(p_h, p_ew, 0, bias1, p_cur, p_acc, batch, M_COPY | M_STATS, 0);

    // 12 hidden convs (6 blocks x 2)
    for (int j = 0; j < 12; j++) {
        int l = j + 1;
        k_gemm<<<GB, 128>>>(p_cur, hWlin + j*CC*CC, p_h, j);
        int mode;
        if (j == 11)      mode = M_SKIP | M_POOL;           // last: skip + relu + pool
        else if (j & 1)   mode = M_SKIP | M_STATS;          // end of block: dense skip
        else              mode = M_STATS;
        k_agg <<<AB, 256>>>(p_h, p_ew + l*NE, l, hbias + j*CC, p_cur, p_acc, batch, mode, j + 1);
    }

    k_final<<<(NG + 63)/64, 64>>>(linW, linb, out);
}

// round 4
// speedup vs baseline: 1.1537x; 1.1537x over previous
#include <cuda_runtime.h>
#include <math.h>

#define NN 50000
#define NE 800000
#define NG 500
#define CC 64
#define NL 13          // 1 + 12 PDN convs
#define LSTRIDE 292    // per-layer smem stride for edge MLP weights

// modes for k_agg epilogue
#define M_COPY  1
#define M_SKIP  2
#define M_POOL  8

// ---------------- scratch (device globals; no allocation) ----------------
__device__ float  g_h  [NN*CC];
__device__ float  g_cur[NN*CC];
__device__ float  g_acc[NN*CC];
__device__ float  g_ew [NL*NE];     // raw ew (CSR order) -> scaled to norm in k_norm
__device__ float  g_deg[NN*16];     // [node][16] deg -> rsqrt(deg) in place
__device__ int    g_cnt[NN];
__device__ int    g_rowptr[NN+1];
__device__ int    g_cursor[NN];
__device__ int    g_eid [NE];
__device__ int    g_csrc[NE];
__device__ int    g_cdst[NE];
__device__ double g_colsum[13*64];
__device__ double g_colsq [13*64];
__device__ float  g_pool[NG*CC];

// ---------------- init ----------------
__global__ void k_reset() {
    int i = blockIdx.x*blockDim.x + threadIdx.x;
    if (i < NN*16) g_deg[i] = 1.0f;          // deg starts at self-loop weight 1
    if (i < NN)    g_cnt[i] = 0;
    if (i < NG*CC) g_pool[i] = 0.0f;
    if (i < 13*64) { g_colsum[i] = 0.0; g_colsq[i] = 0.0; }
}

// ---------------- CSR build ----------------
__global__ void k_hist(const int* __restrict__ dst) {
    int e = blockIdx.x*blockDim.x + threadIdx.x;
    if (e < NE) atomicAdd(&g_cnt[dst[e]], 1);
}

// single-block chunked scan: 1024 threads, 49 chunks
__global__ void k_scanall() {
    __shared__ int wsum[32];
    int t = threadIdx.x;
    int lane = t & 31, wid = t >> 5;
    int carry = 0;
    for (int base = 0; base < NN; base += 1024) {
        int i = base + t;
        int v = (i < NN) ? g_cnt[i] : 0;
        int x = v;
        #pragma unroll
        for (int off = 1; off < 32; off <<= 1) {
            int u = __shfl_up_sync(0xffffffffu, x, off);
            if (lane >= off) x += u;
        }
        if (lane == 31) wsum[wid] = x;
        __syncthreads();
        if (wid == 0) {
            int y = wsum[lane];
            #pragma unroll
            for (int off = 1; off < 32; off <<= 1) {
                int u = __shfl_up_sync(0xffffffffu, y, off);
                if (lane >= off) y += u;
            }
            wsum[lane] = y;
        }
        __syncthreads();
        int pre = (wid > 0) ? wsum[wid-1] : 0;
        int excl = carry + pre + x - v;
        if (i < NN) { g_rowptr[i] = excl; g_cursor[i] = excl; }
        int tot = wsum[31];
        __syncthreads();
        carry += tot;
    }
    if (t == 0) g_rowptr[NN] = carry;
}

__global__ void k_scatter(const int* __restrict__ src, const int* __restrict__ dst) {
    int e = blockIdx.x*blockDim.x + threadIdx.x;
    if (e >= NE) return;
    int d = dst[e];
    int p = atomicAdd(&g_cursor[d], 1);
    g_eid[p]  = e;
    g_csrc[p] = src[e];
    g_cdst[p] = d;
}

// ---------------- edge MLPs: all 13 layers in one pass (NE divisible by 256) ----------------
__global__ __launch_bounds__(256) void k_edgemlp(
    const float* __restrict__ ea,
    const float* __restrict__ m1W, const float* __restrict__ m1b,
    const float* __restrict__ m2W, const float* __restrict__ m2b,
    const float* __restrict__ hm1W, const float* __restrict__ hm1b,
    const float* __restrict__ hm2W, const float* __restrict__ hm2b)
{
    __shared__ __align__(16) float sw[NL*LSTRIDE];
    // per layer l at sw+l*LSTRIDE: [0..255] W1^T (W1T[j*16+i]=W1[i][j]),
    // [256..271] b1, [272..287] W2, [288] b2
    for (int idx = threadIdx.x; idx < NL*LSTRIDE; idx += 256) {
        int l = idx / LSTRIDE, r = idx - l*LSTRIDE;
        float v = 0.0f;
        if (r < 256) {
            int j = r >> 4, i = r & 15;
            v = (l == 0) ? m1W[i*16 + j] : hm1W[(l-1)*256 + i*16 + j];
        } else if (r < 272) {
            v = (l == 0) ? m1b[r-256] : hm1b[(l-1)*16 + (r-256)];
        } else if (r < 288) {
            v = (l == 0) ? m2W[r-272] : hm2W[(l-1)*16 + (r-272)];
        } else if (r == 288) {
            v = (l == 0) ? m2b[0] : hm2b[l-1];
        }
        sw[idx] = v;
    }
    __syncthreads();

    int p = blockIdx.x*256 + threadIdx.x;   // always < NE
    int e = g_eid[p];
    int d = g_cdst[p];

    float a[16];
    const float4* ap = (const float4*)(ea + e*16);
    #pragma unroll
    for (int q = 0; q < 4; q++) {
        float4 v = ap[q];
        a[4*q+0]=v.x; a[4*q+1]=v.y; a[4*q+2]=v.z; a[4*q+3]=v.w;
    }

    #pragma unroll 1
    for (int l = 0; l < NL; l++) {
        const float* W = &sw[l*LSTRIDE];
        float z = W[288];
        #pragma unroll
        for (int j = 0; j < 16; j++) {
            const float4* wc = (const float4*)&W[j*16];
            float4 w0 = wc[0], w1 = wc[1], w2 = wc[2], w3 = wc[3];
            float t = W[256+j];
            t=fmaf(a[0],w0.x,t); t=fmaf(a[1],w0.y,t); t=fmaf(a[2],w0.z,t); t=fmaf(a[3],w0.w,t);
            t=fmaf(a[4],w1.x,t); t=fmaf(a[5],w1.y,t); t=fmaf(a[6],w1.z,t); t=fmaf(a[7],w1.w,t);
            t=fmaf(a[8],w2.x,t); t=fmaf(a[9],w2.y,t); t=fmaf(a[10],w2.z,t); t=fmaf(a[11],w2.w,t);
            t=fmaf(a[12],w3.x,t); t=fmaf(a[13],w3.y,t); t=fmaf(a[14],w3.z,t); t=fmaf(a[15],w3.w,t);
            t = fmaxf(t, 0.0f);
            z = fmaf(t, W[272+j], z);
        }
        float ew = 1.0f / (1.0f + __expf(-z));
        g_ew[l*NE + p] = ew;
        atomicAdd(&g_deg[d*16 + l], ew);   // 13 layers hit the same 64B line
    }
}

__global__ void k_rsqrt() {
    int i = blockIdx.x*blockDim.x + threadIdx.x;
    if (i < NN*16) g_deg[i] = rsqrtf(g_deg[i]);   // deg >= 1 always
}

__global__ void k_norm() {
    int p = blockIdx.x*256 + threadIdx.x;   // always < NE
    int s = g_csrc[p], d = g_cdst[p];
    float ds[16], dd[16];
    const float4* sp = (const float4*)(g_deg + s*16);
    const float4* dp = (const float4*)(g_deg + d*16);
    #pragma unroll
    for (int q = 0; q < 4; q++) {
        float4 v = sp[q]; ds[4*q]=v.x; ds[4*q+1]=v.y; ds[4*q+2]=v.z; ds[4*q+3]=v.w;
        float4 u = dp[q]; dd[4*q]=u.x; dd[4*q+1]=u.y; dd[4*q+2]=u.z; dd[4*q+3]=u.w;
    }
    #pragma unroll
    for (int l = 0; l < NL; l++)
        g_ew[l*NE + p] *= ds[l]*dd[l];
}

// ---------------- fused BN+ReLU+GEMM, 1 row/thread (R2-proven) ----------------
#define GSTEP(AV, KIDX) {                                             \
    const float4* wr = (const float4*)&sW[(KIDX)*64];                 \
    _Pragma("unroll")                                                 \
    for (int j = 0; j < 16; j++) {                                    \
        float4 w = wr[j];                                             \
        acc[4*j+0] = fmaf((AV), w.x, acc[4*j+0]);                     \
        acc[4*j+1] = fmaf((AV), w.y, acc[4*j+1]);                     \
        acc[4*j+2] = fmaf((AV), w.z, acc[4*j+2]);                     \
        acc[4*j+3] = fmaf((AV), w.w, acc[4*j+3]);                     \
    } }

__global__ __launch_bounds__(128) void k_gemm(
    const float* __restrict__ A, const float* __restrict__ W,
    float* __restrict__ H, int slot)     // slot < 0 : no BN
{
    __shared__ __align__(16) float sW[64*64];
    __shared__ float smu[64], ssc[64];
    int t = threadIdx.x;
    const float4* W4 = (const float4*)W;
    float4* sW4 = (float4*)sW;
    #pragma unroll
    for (int i = 0; i < 8; i++) sW4[t + i*128] = W4[t + i*128];
    if (slot >= 0 && t < 64) {
        double mu  = g_colsum[slot*64 + t] / (double)NN;
        double var = g_colsq[slot*64 + t] / (double)NN - mu*mu;
        if (var < 0.0) var = 0.0;
        smu[t] = (float)mu;
        ssc[t] = (float)(1.0 / sqrt(var + 1e-5));
    }
    __syncthreads();

    int r = blockIdx.x*128 + t;
    if (r >= NN) return;
    const float4* A4 = (const float4*)(A + r*64);
    float acc[64];
    #pragma unroll
    for (int j = 0; j < 64; j++) acc[j] = 0.0f;

    #pragma unroll 4
    for (int g = 0; g < 16; g++) {
        float4 av = A4[g];
        if (slot >= 0) {
            av.x = fmaxf((av.x - smu[4*g+0]) * ssc[4*g+0], 0.0f);
            av.y = fmaxf((av.y - smu[4*g+1]) * ssc[4*g+1], 0.0f);
            av.z = fmaxf((av.z - smu[4*g+2]) * ssc[4*g+2], 0.0f);
            av.w = fmaxf((av.w - smu[4*g+3]) * ssc[4*g+3], 0.0f);
        }
        GSTEP(av.x, 4*g+0);
        GSTEP(av.y, 4*g+1);
        GSTEP(av.z, 4*g+2);
        GSTEP(av.w, 4*g+3);
    }
    float4* H4 = (float4*)(H + r*64);
    #pragma unroll
    for (int j = 0; j < 16; j++) {
        float4 o; o.x=acc[4*j]; o.y=acc[4*j+1]; o.z=acc[4*j+2]; o.w=acc[4*j+3];
        H4[j] = o;
    }
}

// ---------------- BN statistics (standalone, slot-indexed) ----------------
__global__ void k_bnstats(const float* __restrict__ A, int slot) {
    int t = threadIdx.x;
    int c = t & 63, rg = t >> 6;              // 256 threads: 4 row lanes x 64 cols
    double s = 0.0, q = 0.0;
    for (int r = blockIdx.x*4 + rg; r < NN; r += gridDim.x*4) {
        float v = A[r*64 + c];
        s += v; q += (double)v * v;
    }
    __shared__ double ss[256], sq[256];
    ss[t] = s; sq[t] = q; __syncthreads();
    if (t < 64) {
        double S = ss[t] + ss[t+64] + ss[t+128] + ss[t+192];
        double Q = sq[t] + sq[t+64] + sq[t+128] + sq[t+192];
        atomicAdd(&g_colsum[slot*64 + c], S);
        atomicAdd(&g_colsq [slot*64 + c], Q);
    }
}

// ---------------- CSR aggregation + fused elementwise epilogues (no syncs) ----------------
__global__ __launch_bounds__(256) void k_agg(
    const float* __restrict__ h, const float* __restrict__ nrm,
    int layer, const float* __restrict__ bias,
    float* __restrict__ cur, float* __restrict__ acc,
    const int* __restrict__ batch, int mode)
{
    int t = threadIdx.x;
    int w = (blockIdx.x*256 + t) >> 5;
    int lane = t & 31;
    if (w >= NN) return;
    int c = lane*2;
    float dv = g_deg[w*16 + layer];
    float selfw = dv*dv;
    float2 hv = *(const float2*)(h + w*64 + c);
    float ax = fmaf(selfw, hv.x, bias[c]);
    float ay = fmaf(selfw, hv.y, bias[c+1]);
    int p0 = g_rowptr[w], p1 = g_rowptr[w+1];
    int p = p0;
    for (; p + 3 < p1; p += 4) {
        int s0 = g_csrc[p],   s1 = g_csrc[p+1];
        int s2 = g_csrc[p+2], s3 = g_csrc[p+3];
        float w0 = nrm[p],   w1 = nrm[p+1];
        float w2 = nrm[p+2], w3 = nrm[p+3];
        float2 v0 = *(const float2*)(h + s0*64 + c);
        float2 v1 = *(const float2*)(h + s1*64 + c);
        float2 v2 = *(const float2*)(h + s2*64 + c);
        float2 v3 = *(const float2*)(h + s3*64 + c);
        ax = fmaf(w0, v0.x, ax); ay = fmaf(w0, v0.y, ay);
        ax = fmaf(w1, v1.x, ax); ay = fmaf(w1, v1.y, ay);
        ax = fmaf(w2, v2.x, ax); ay = fmaf(w2, v2.y, ay);
        ax = fmaf(w3, v3.x, ax); ay = fmaf(w3, v3.y, ay);
    }
    for (; p < p1; p++) {
        int s = g_csrc[p];
        float wt = nrm[p];
        float2 v = *(const float2*)(h + s*64 + c);
        ax = fmaf(wt, v.x, ax);
        ay = fmaf(wt, v.y, ay);
    }
    if (mode & M_SKIP) {
        float2 a2 = *(float2*)(acc + w*64 + c);
        ax += a2.x; ay += a2.y;
        a2.x += ax; a2.y += ay;
        *(float2*)(acc + w*64 + c) = a2;
    }
    float2 o; o.x = ax; o.y = ay;
    *(float2*)(cur + w*64 + c) = o;
    if (mode & M_COPY) *(float2*)(acc + w*64 + c) = o;
    if (mode & M_POOL) {
        float rx = fmaxf(ax, 0.0f), ry = fmaxf(ay, 0.0f);
        int b = batch[w];
        atomicMax((int*)&g_pool[b*64 + c],     __float_as_int(rx));
        atomicMax((int*)&g_pool[b*64 + c + 1], __float_as_int(ry));
    }
}

// ---------------- readout ----------------
__global__ void k_final(const float* __restrict__ linW, const float* __restrict__ linb,
                        float* __restrict__ out) {
    int g = blockIdx.x*blockDim.x + threadIdx.x;
    if (g >= NG) return;
    float a0 = linb[0], a1 = linb[1];
    #pragma unroll 8
    for (int c = 0; c < CC; c++) {
        float v = g_pool[g*64 + c];
        a0 = fmaf(v, linW[c*2+0], a0);
        a1 = fmaf(v, linW[c*2+1], a1);
    }
    out[g*2+0] = a0;
    out[g*2+1] = a1;
}

// ---------------- launch ----------------
extern "C" void kernel_launch(void* const* d_in, const int* in_sizes, int n_in,
                              void* d_out, int out_size)
{
    const float* x     = (const float*)d_in[0];
    const int*   ei    = (const int*)  d_in[1];
    const int*   batch = (const int*)  d_in[2];
    /* d_in[3] = dropout (unused, eval mode) */
    const float* ea    = (const float*)d_in[4];
    const float* Wlin1 = (const float*)d_in[5];
    const float* bias1 = (const float*)d_in[6];
    const float* m1W1  = (const float*)d_in[7];
    const float* m1b1  = (const float*)d_in[8];
    const float* m2W1  = (const float*)d_in[9];
    const float* m2b1  = (const float*)d_in[10];
    const float* hWlin = (const float*)d_in[11];
    const float* hbias = (const float*)d_in[12];
    const float* hm1W  = (const float*)d_in[13];
    const float* hm1b  = (const float*)d_in[14];
    const float* hm2W  = (const float*)d_in[15];
    const float* hm2b  = (const float*)d_in[16];
    const float* linW  = (const float*)d_in[17];
    const float* linb  = (const float*)d_in[18];
    float* out = (float*)d_out;

    const int* src = ei;
    const int* dst = ei + NE;

    float *p_h, *p_cur, *p_acc, *p_ew;
    cudaGetSymbolAddress((void**)&p_h,   g_h);
    cudaGetSymbolAddress((void**)&p_cur, g_cur);
    cudaGetSymbolAddress((void**)&p_acc, g_acc);
    cudaGetSymbolAddress((void**)&p_ew,  g_ew);

    const int EB = NE / 256;                  // 3125 (exact)
    const int GB = (NN + 127) / 128;          // 391
    const int AB = (NN*32) / 256;             // 6250 (exact)

    // prologue: CSR + all edge norms for all 13 layers
    k_reset  <<<(NN*16 + 255)/256, 256>>>();
    k_hist   <<<EB, 256>>>(dst);
    k_scanall<<<1, 1024>>>();
    k_scatter<<<EB, 256>>>(src, dst);
    k_edgemlp<<<EB, 256>>>(ea, m1W1, m1b1, m2W1, m2b1, hm1W, hm1b, hm2W, hm2b);
    k_rsqrt  <<<(NN*16 + 255)/256, 256>>>();
    k_norm   <<<EB, 256>>>();

    // conv1
    k_gemm<<<GB, 128>>>(x, Wlin1, p_h, -1);
    k_agg <<<AB, 256>>>(p_h, p_ew, 0, bias1, p_cur, p_acc, batch, M_COPY);

    // 12 hidden convs (6 blocks x 2)
    for (int j = 0; j < 12; j++) {
        int l = j + 1;
        k_bnstats<<<256, 256>>>(p_cur, j);
        k_gemm<<<GB, 128>>>(p_cur, hWlin + j*CC*CC, p_h, j);
        int mode;
        if (j == 11)      mode = M_SKIP | M_POOL;   // last: skip + relu + pool
        else if (j & 1)   mode = M_SKIP;            // end of block: dense skip
        else              mode = 0;
        k_agg <<<AB, 256>>>(p_h, p_ew + l*NE, l, hbias + j*CC, p_cur, p_acc, batch, mode);
    }

    k_final<<<(NG + 63)/64, 64>>>(linW, linb, out);
}

// round 5
// speedup vs baseline: 1.3217x; 1.1456x over previous
#include <cuda_runtime.h>
#include <cuda_fp16.h>
#include <math.h>

#define NN 50000
#define NE 800000
#define NG 500
#define CC 64
#define NL 13          // 1 + 12 PDN convs
#define LSTRIDE 292    // per-layer smem stride for edge MLP weights

// modes for k_agg epilogue
#define M_COPY  1
#define M_SKIP  2
#define M_POOL  8

// ---------------- scratch (device globals; no allocation) ----------------
__device__ __half g_h  [NN*CC];     // fp16 GEMM output (gather bandwidth halved)
__device__ float  g_cur[NN*CC];
__device__ float  g_acc[NN*CC];
__device__ float  g_ew [NL*NE];     // raw ew (CSR order) -> scaled to norm in k_norm
__device__ float  g_deg[NN*16];     // [node][16] deg -> rsqrt(deg) in place
__device__ int    g_cnt[NN];
__device__ int    g_rowptr[NN+1];
__device__ int    g_cursor[NN];
__device__ int    g_eid [NE];
__device__ int    g_csrc[NE];
__device__ int    g_cdst[NE];
__device__ double g_colsum[13*64];
__device__ double g_colsq [13*64];
__device__ float  g_pool[NG*CC];

// ---------------- init ----------------
__global__ void k_reset() {
    int i = blockIdx.x*blockDim.x + threadIdx.x;
    if (i < NN*16) g_deg[i] = 1.0f;          // deg starts at self-loop weight 1
    if (i < NN)    g_cnt[i] = 0;
    if (i < NG*CC) g_pool[i] = 0.0f;
    if (i < 13*64) { g_colsum[i] = 0.0; g_colsq[i] = 0.0; }
}

// ---------------- CSR build ----------------
__global__ void k_hist(const int* __restrict__ dst) {
    int e = blockIdx.x*blockDim.x + threadIdx.x;
    if (e < NE) atomicAdd(&g_cnt[dst[e]], 1);
}

// single-block chunked scan: 1024 threads, 49 chunks
__global__ void k_scanall() {
    __shared__ int wsum[32];
    int t = threadIdx.x;
    int lane = t & 31, wid = t >> 5;
    int carry = 0;
    for (int base = 0; base < NN; base += 1024) {
        int i = base + t;
        int v = (i < NN) ? g_cnt[i] : 0;
        int x = v;
        #pragma unroll
        for (int off = 1; off < 32; off <<= 1) {
            int u = __shfl_up_sync(0xffffffffu, x, off);
            if (lane >= off) x += u;
        }
        if (lane == 31) wsum[wid] = x;
        __syncthreads();
        if (wid == 0) {
            int y = wsum[lane];
            #pragma unroll
            for (int off = 1; off < 32; off <<= 1) {
                int u = __shfl_up_sync(0xffffffffu, y, off);
                if (lane >= off) y += u;
            }
            wsum[lane] = y;
        }
        __syncthreads();
        int pre = (wid > 0) ? wsum[wid-1] : 0;
        int excl = carry + pre + x - v;
        if (i < NN) { g_rowptr[i] = excl; g_cursor[i] = excl; }
        int tot = wsum[31];
        __syncthreads();
        carry += tot;
    }
    if (t == 0) g_rowptr[NN] = carry;
}

__global__ void k_scatter(const int* __restrict__ src, const int* __restrict__ dst) {
    int e = blockIdx.x*blockDim.x + threadIdx.x;
    if (e >= NE) return;
    int d = dst[e];
    int p = atomicAdd(&g_cursor[d], 1);
    g_eid[p]  = e;
    g_csrc[p] = src[e];
    g_cdst[p] = d;
}

// ---------------- edge MLPs: all 13 layers in one pass (NE divisible by 256) ----------------
__global__ __launch_bounds__(256) void k_edgemlp(
    const float* __restrict__ ea,
    const float* __restrict__ m1W, const float* __restrict__ m1b,
    const float* __restrict__ m2W, const float* __restrict__ m2b,
    const float* __restrict__ hm1W, const float* __restrict__ hm1b,
    const float* __restrict__ hm2W, const float* __restrict__ hm2b)
{
    __shared__ __align__(16) float sw[NL*LSTRIDE];
    // per layer l at sw+l*LSTRIDE: [0..255] W1^T (W1T[j*16+i]=W1[i][j]),
    // [256..271] b1, [272..287] W2, [288] b2
    for (int idx = threadIdx.x; idx < NL*LSTRIDE; idx += 256) {
        int l = idx / LSTRIDE, r = idx - l*LSTRIDE;
        float v = 0.0f;
        if (r < 256) {
            int j = r >> 4, i = r & 15;
            v = (l == 0) ? m1W[i*16 + j] : hm1W[(l-1)*256 + i*16 + j];
        } else if (r < 272) {
            v = (l == 0) ? m1b[r-256] : hm1b[(l-1)*16 + (r-256)];
        } else if (r < 288) {
            v = (l == 0) ? m2W[r-272] : hm2W[(l-1)*16 + (r-272)];
        } else if (r == 288) {
            v = (l == 0) ? m2b[0] : hm2b[l-1];
        }
        sw[idx] = v;
    }
    __syncthreads();

    int p = blockIdx.x*256 + threadIdx.x;   // always < NE
    int e = g_eid[p];
    int d = g_cdst[p];

    float a[16];
    const float4* ap = (const float4*)(ea + e*16);
    #pragma unroll
    for (int q = 0; q < 4; q++) {
        float4 v = ap[q];
        a[4*q+0]=v.x; a[4*q+1]=v.y; a[4*q+2]=v.z; a[4*q+3]=v.w;
    }

    #pragma unroll 1
    for (int l = 0; l < NL; l++) {
        const float* W = &sw[l*LSTRIDE];
        float z = W[288];
        #pragma unroll
        for (int j = 0; j < 16; j++) {
            const float4* wc = (const float4*)&W[j*16];
            float4 w0 = wc[0], w1 = wc[1], w2 = wc[2], w3 = wc[3];
            float t = W[256+j];
            t=fmaf(a[0],w0.x,t); t=fmaf(a[1],w0.y,t); t=fmaf(a[2],w0.z,t); t=fmaf(a[3],w0.w,t);
            t=fmaf(a[4],w1.x,t); t=fmaf(a[5],w1.y,t); t=fmaf(a[6],w1.z,t); t=fmaf(a[7],w1.w,t);
            t=fmaf(a[8],w2.x,t); t=fmaf(a[9],w2.y,t); t=fmaf(a[10],w2.z,t); t=fmaf(a[11],w2.w,t);
            t=fmaf(a[12],w3.x,t); t=fmaf(a[13],w3.y,t); t=fmaf(a[14],w3.z,t); t=fmaf(a[15],w3.w,t);
            t = fmaxf(t, 0.0f);
            z = fmaf(t, W[272+j], z);
        }
        float ew = 1.0f / (1.0f + __expf(-z));
        g_ew[l*NE + p] = ew;
        atomicAdd(&g_deg[d*16 + l], ew);   // 13 layers hit the same 64B line
    }
}

__global__ void k_rsqrt() {
    int i = blockIdx.x*blockDim.x + threadIdx.x;
    if (i < NN*16) g_deg[i] = rsqrtf(g_deg[i]);   // deg >= 1 always
}

__global__ void k_norm() {
    int p = blockIdx.x*256 + threadIdx.x;   // always < NE
    int s = g_csrc[p], d = g_cdst[p];
    float ds[16], dd[16];
    const float4* sp = (const float4*)(g_deg + s*16);
    const float4* dp = (const float4*)(g_deg + d*16);
    #pragma unroll
    for (int q = 0; q < 4; q++) {
        float4 v = sp[q]; ds[4*q]=v.x; ds[4*q+1]=v.y; ds[4*q+2]=v.z; ds[4*q+3]=v.w;
        float4 u = dp[q]; dd[4*q]=u.x; dd[4*q+1]=u.y; dd[4*q+2]=u.z; dd[4*q+3]=u.w;
    }
    #pragma unroll
    for (int l = 0; l < NL; l++)
        g_ew[l*NE + p] *= ds[l]*dd[l];
}

// ---------------- fused BN+ReLU+GEMM, 1 row/thread, fp16 output ----------------
#define GSTEP(AV, KIDX) {                                             \
    const float4* wr = (const float4*)&sW[(KIDX)*64];                 \
    _Pragma("unroll")                                                 \
    for (int j = 0; j < 16; j++) {                                    \
        float4 w = wr[j];                                             \
        acc[4*j+0] = fmaf((AV), w.x, acc[4*j+0]);                     \
        acc[4*j+1] = fmaf((AV), w.y, acc[4*j+1]);                     \
        acc[4*j+2] = fmaf((AV), w.z, acc[4*j+2]);                     \
        acc[4*j+3] = fmaf((AV), w.w, acc[4*j+3]);                     \
    } }

__global__ __launch_bounds__(128) void k_gemm(
    const float* __restrict__ A, const float* __restrict__ W,
    __half* __restrict__ H, int slot)     // slot < 0 : no BN
{
    __shared__ __align__(16) float sW[64*64];
    __shared__ float smu[64], ssc[64];
    int t = threadIdx.x;
    const float4* W4 = (const float4*)W;
    float4* sW4 = (float4*)sW;
    #pragma unroll
    for (int i = 0; i < 8; i++) sW4[t + i*128] = W4[t + i*128];
    if (slot >= 0 && t < 64) {
        double mu  = g_colsum[slot*64 + t] / (double)NN;
        double var = g_colsq[slot*64 + t] / (double)NN - mu*mu;
        if (var < 0.0) var = 0.0;
        smu[t] = (float)mu;
        ssc[t] = (float)(1.0 / sqrt(var + 1e-5));
    }
    __syncthreads();

    int r = blockIdx.x*128 + t;
    if (r >= NN) return;
    const float4* A4 = (const float4*)(A + r*64);
    float acc[64];
    #pragma unroll
    for (int j = 0; j < 64; j++) acc[j] = 0.0f;

    #pragma unroll 4
    for (int g = 0; g < 16; g++) {
        float4 av = A4[g];
        if (slot >= 0) {
            av.x = fmaxf((av.x - smu[4*g+0]) * ssc[4*g+0], 0.0f);
            av.y = fmaxf((av.y - smu[4*g+1]) * ssc[4*g+1], 0.0f);
            av.z = fmaxf((av.z - smu[4*g+2]) * ssc[4*g+2], 0.0f);
            av.w = fmaxf((av.w - smu[4*g+3]) * ssc[4*g+3], 0.0f);
        }
        GSTEP(av.x, 4*g+0);
        GSTEP(av.y, 4*g+1);
        GSTEP(av.z, 4*g+2);
        GSTEP(av.w, 4*g+3);
    }
    // pack to fp16 and store 128B as 8x uint4
    uint4* H4 = (uint4*)(H + r*64);
    #pragma unroll
    for (int j = 0; j < 8; j++) {
        union { __half2 h2[4]; uint4 u; } pk;
        pk.h2[0] = __floats2half2_rn(acc[8*j+0], acc[8*j+1]);
        pk.h2[1] = __floats2half2_rn(acc[8*j+2], acc[8*j+3]);
        pk.h2[2] = __floats2half2_rn(acc[8*j+4], acc[8*j+5]);
        pk.h2[3] = __floats2half2_rn(acc[8*j+6], acc[8*j+7]);
        H4[j] = pk.u;
    }
}

// ---------------- BN statistics (fp32 per-thread accumulation, fp64 reduce) ----------------
__global__ void k_bnstats(const float* __restrict__ A, int slot) {
    int t = threadIdx.x;
    int c = t & 63, rg = t >> 6;              // 256 threads: 4 row lanes x 64 cols
    float s = 0.0f, q = 0.0f;                 // ~49 elements per thread: fp32 is exact enough
    for (int r = blockIdx.x*4 + rg; r < NN; r += gridDim.x*4) {
        float v = A[r*64 + c];
        s += v; q = fmaf(v, v, q);
    }
    __shared__ float ss[256], sq[256];
    ss[t] = s; sq[t] = q; __syncthreads();
    if (t < 64) {
        double S = (double)ss[t] + (double)ss[t+64] + (double)ss[t+128] + (double)ss[t+192];
        double Q = (double)sq[t] + (double)sq[t+64] + (double)sq[t+128] + (double)sq[t+192];
        atomicAdd(&g_colsum[slot*64 + c], S);
        atomicAdd(&g_colsq [slot*64 + c], Q);
    }
}

// ---------------- CSR aggregation (fp16 gathers, fp32 accumulate) + epilogues ----------------
__global__ __launch_bounds__(256) void k_agg(
    const __half* __restrict__ h, const float* __restrict__ nrm,
    int layer, const float* __restrict__ bias,
    float* __restrict__ cur, float* __restrict__ acc,
    const int* __restrict__ batch, int mode)
{
    int t = threadIdx.x;
    int w = (blockIdx.x*256 + t) >> 5;
    int lane = t & 31;
    if (w >= NN) return;
    int c = lane*2;
    float dv = g_deg[w*16 + layer];
    float selfw = dv*dv;
    float2 hv = __half22float2(*(const __half2*)(h + w*64 + c));
    float ax = fmaf(selfw, hv.x, bias[c]);
    float ay = fmaf(selfw, hv.y, bias[c+1]);
    int p0 = g_rowptr[w], p1 = g_rowptr[w+1];
    int p = p0;
    for (; p + 3 < p1; p += 4) {
        int s0 = g_csrc[p],   s1 = g_csrc[p+1];
        int s2 = g_csrc[p+2], s3 = g_csrc[p+3];
        float w0 = nrm[p],   w1 = nrm[p+1];
        float w2 = nrm[p+2], w3 = nrm[p+3];
        float2 v0 = __half22float2(*(const __half2*)(h + s0*64 + c));
        float2 v1 = __half22float2(*(const __half2*)(h + s1*64 + c));
        float2 v2 = __half22float2(*(const __half2*)(h + s2*64 + c));
        float2 v3 = __half22float2(*(const __half2*)(h + s3*64 + c));
        ax = fmaf(w0, v0.x, ax); ay = fmaf(w0, v0.y, ay);
        ax = fmaf(w1, v1.x, ax); ay = fmaf(w1, v1.y, ay);
        ax = fmaf(w2, v2.x, ax); ay = fmaf(w2, v2.y, ay);
        ax = fmaf(w3, v3.x, ax); ay = fmaf(w3, v3.y, ay);
    }
    for (; p < p1; p++) {
        int s = g_csrc[p];
        float wt = nrm[p];
        float2 v = __half22float2(*(const __half2*)(h + s*64 + c));
        ax = fmaf(wt, v.x, ax);
        ay = fmaf(wt, v.y, ay);
    }
    if (mode & M_SKIP) {
        float2 a2 = *(float2*)(acc + w*64 + c);
        ax += a2.x; ay += a2.y;
        a2.x += ax; a2.y += ay;
        *(float2*)(acc + w*64 + c) = a2;
    }
    float2 o; o.x = ax; o.y = ay;
    *(float2*)(cur + w*64 + c) = o;
    if (mode & M_COPY) *(float2*)(acc + w*64 + c) = o;
    if (mode & M_POOL) {
        float rx = fmaxf(ax, 0.0f), ry = fmaxf(ay, 0.0f);
        int b = batch[w];
        atomicMax((int*)&g_pool[b*64 + c],     __float_as_int(rx));
        atomicMax((int*)&g_pool[b*64 + c + 1], __float_as_int(ry));
    }
}

// ---------------- readout ----------------
__global__ void k_final(const float* __restrict__ linW, const float* __restrict__ linb,
                        float* __restrict__ out) {
    int g = blockIdx.x*blockDim.x + threadIdx.x;
    if (g >= NG) return;
    float a0 = linb[0], a1 = linb[1];
    #pragma unroll 8
    for (int c = 0; c < CC; c++) {
        float v = g_pool[g*64 + c];
        a0 = fmaf(v, linW[c*2+0], a0);
        a1 = fmaf(v, linW[c*2+1], a1);
    }
    out[g*2+0] = a0;
    out[g*2+1] = a1;
}

// ---------------- launch ----------------
extern "C" void kernel_launch(void* const* d_in, const int* in_sizes, int n_in,
                              void* d_out, int out_size)
{
    const float* x     = (const float*)d_in[0];
    const int*   ei    = (const int*)  d_in[1];
    const int*   batch = (const int*)  d_in[2];
    /* d_in[3] = dropout (unused, eval mode) */
    const float* ea    = (const float*)d_in[4];
    const float* Wlin1 = (const float*)d_in[5];
    const float* bias1 = (const float*)d_in[6];
    const float* m1W1  = (const float*)d_in[7];
    const float* m1b1  = (const float*)d_in[8];
    const float* m2W1  = (const float*)d_in[9];
    const float* m2b1  = (const float*)d_in[10];
    const float* hWlin = (const float*)d_in[11];
    const float* hbias = (const float*)d_in[12];
    const float* hm1W  = (const float*)d_in[13];
    const float* hm1b  = (const float*)d_in[14];
    const float* hm2W  = (const float*)d_in[15];
    const float* hm2b  = (const float*)d_in[16];
    const float* linW  = (const float*)d_in[17];
    const float* linb  = (const float*)d_in[18];
    float* out = (float*)d_out;

    const int* src = ei;
    const int* dst = ei + NE;

    __half *p_h;
    float *p_cur, *p_acc, *p_ew;
    cudaGetSymbolAddress((void**)&p_h,   g_h);
    cudaGetSymbolAddress((void**)&p_cur, g_cur);
    cudaGetSymbolAddress((void**)&p_acc, g_acc);
    cudaGetSymbolAddress((void**)&p_ew,  g_ew);

    const int EB = NE / 256;                  // 3125 (exact)
    const int GB = (NN + 127) / 128;          // 391
    const int AB = (NN*32) / 256;             // 6250 (exact)

    // prologue: CSR + all edge norms for all 13 layers
    k_reset  <<<(NN*16 + 255)/256, 256>>>();
    k_hist   <<<EB, 256>>>(dst);
    k_scanall<<<1, 1024>>>();
    k_scatter<<<EB, 256>>>(src, dst);
    k_edgemlp<<<EB, 256>>>(ea, m1W1, m1b1, m2W1, m2b1, hm1W, hm1b, hm2W, hm2b);
    k_rsqrt  <<<(NN*16 + 255)/256, 256>>>();
    k_norm   <<<EB, 256>>>();

    // conv1
    k_gemm<<<GB, 128>>>(x, Wlin1, p_h, -1);
    k_agg <<<AB, 256>>>(p_h, p_ew, 0, bias1, p_cur, p_acc, batch, M_COPY);

    // 12 hidden convs (6 blocks x 2)
    for (int j = 0; j < 12; j++) {
        int l = j + 1;
        k_bnstats<<<256, 256>>>(p_cur, j);
        k_gemm<<<GB, 128>>>(p_cur, hWlin + j*CC*CC, p_h, j);
        int mode;
        if (j == 11)      mode = M_SKIP | M_POOL;   // last: skip + relu + pool
        else if (j & 1)   mode = M_SKIP;            // end of block: dense skip
        else              mode = 0;
        k_agg <<<AB, 256>>>(p_h, p_ew + l*NE, l, hbias + j*CC, p_cur, p_acc, batch, mode);
    }

    k_final<<<(NG + 63)/64, 64>>>(linW, linb, out);
}

// round 6
// speedup vs baseline: 1.3329x; 1.0084x over previous
#include <cuda_runtime.h>
#include <cuda_fp16.h>
#include <math.h>

#define NN 50000
#define NE 800000
#define NG 500
#define CC 64
#define NL 13          // 1 + 12 PDN convs
#define LSTRIDE 292    // per-layer smem stride for edge MLP weights

// modes for k_agg epilogue
#define M_COPY  1
#define M_SKIP  2
#define M_POOL  8

// ---------------- scratch (device globals; no allocation) ----------------
__device__ __half g_h  [NN*CC];     // fp16 GEMM output (gather bandwidth halved)
__device__ float  g_cur[NN*CC];
__device__ float  g_acc[NN*CC];
__device__ float  g_ew [NL*NE];     // raw ew (CSR order) -> scaled to norm in k_norm
__device__ float  g_deg[NN*16];     // [node][16] deg -> rsqrt(deg) in place
__device__ int    g_cnt[NN];
__device__ int    g_rowptr[NN+1];
__device__ int    g_cursor[NN];
__device__ int    g_eid [NE];
__device__ int    g_csrc[NE];
__device__ int    g_cdst[NE];
__device__ double g_colsum[13*64];
__device__ double g_colsq [13*64];
__device__ float  g_pool[NG*CC];

// ---------------- init ----------------
__global__ void k_reset() {
    int i = blockIdx.x*blockDim.x + threadIdx.x;
    if (i < NN*16) g_deg[i] = 1.0f;          // deg starts at self-loop weight 1
    if (i < NN)    g_cnt[i] = 0;
    if (i < NG*CC) g_pool[i] = 0.0f;
    if (i < 13*64) { g_colsum[i] = 0.0; g_colsq[i] = 0.0; }
}

// ---------------- CSR build ----------------
__global__ void k_hist(const int* __restrict__ dst) {
    int e = blockIdx.x*blockDim.x + threadIdx.x;
    if (e < NE) atomicAdd(&g_cnt[dst[e]], 1);
}

// single-block chunked scan: 1024 threads, 49 chunks
__global__ void k_scanall() {
    __shared__ int wsum[32];
    int t = threadIdx.x;
    int lane = t & 31, wid = t >> 5;
    int carry = 0;
    for (int base = 0; base < NN; base += 1024) {
        int i = base + t;
        int v = (i < NN) ? g_cnt[i] : 0;
        int x = v;
        #pragma unroll
        for (int off = 1; off < 32; off <<= 1) {
            int u = __shfl_up_sync(0xffffffffu, x, off);
            if (lane >= off) x += u;
        }
        if (lane == 31) wsum[wid] = x;
        __syncthreads();
        if (wid == 0) {
            int y = wsum[lane];
            #pragma unroll
            for (int off = 1; off < 32; off <<= 1) {
                int u = __shfl_up_sync(0xffffffffu, y, off);
                if (lane >= off) y += u;
            }
            wsum[lane] = y;
        }
        __syncthreads();
        int pre = (wid > 0) ? wsum[wid-1] : 0;
        int excl = carry + pre + x - v;
        if (i < NN) { g_rowptr[i] = excl; g_cursor[i] = excl; }
        int tot = wsum[31];
        __syncthreads();
        carry += tot;
    }
    if (t == 0) g_rowptr[NN] = carry;
}

__global__ void k_scatter(const int* __restrict__ src, const int* __restrict__ dst) {
    int e = blockIdx.x*blockDim.x + threadIdx.x;
    if (e >= NE) return;
    int d = dst[e];
    int p = atomicAdd(&g_cursor[d], 1);
    g_eid[p]  = e;
    g_csrc[p] = src[e];
    g_cdst[p] = d;
}

// ---------------- edge MLPs: 4 edges/thread, all 13 layers (NE = 4*200000 exact) ----------------
__global__ __launch_bounds__(256) void k_edgemlp(
    const float* __restrict__ ea,
    const float* __restrict__ m1W, const float* __restrict__ m1b,
    const float* __restrict__ m2W, const float* __restrict__ m2b,
    const float* __restrict__ hm1W, const float* __restrict__ hm1b,
    const float* __restrict__ hm2W, const float* __restrict__ hm2b)
{
    __shared__ __align__(16) float sw[NL*LSTRIDE];
    // per layer l at sw+l*LSTRIDE: [0..255] W1^T (W1T[j*16+i]=W1[i][j]),
    // [256..271] b1, [272..287] W2, [288] b2
    for (int idx = threadIdx.x; idx < NL*LSTRIDE; idx += 256) {
        int l = idx / LSTRIDE, r = idx - l*LSTRIDE;
        float v = 0.0f;
        if (r < 256) {
            int j = r >> 4, i = r & 15;
            v = (l == 0) ? m1W[i*16 + j] : hm1W[(l-1)*256 + i*16 + j];
        } else if (r < 272) {
            v = (l == 0) ? m1b[r-256] : hm1b[(l-1)*16 + (r-256)];
        } else if (r < 288) {
            v = (l == 0) ? m2W[r-272] : hm2W[(l-1)*16 + (r-272)];
        } else if (r == 288) {
            v = (l == 0) ? m2b[0] : hm2b[l-1];
        }
        sw[idx] = v;
    }
    __syncthreads();

    int tid = blockIdx.x*256 + threadIdx.x;
    if (tid >= NE/4) return;
    int p0 = tid*4;

    int4 ev = *(const int4*)(g_eid  + p0);
    int4 dv = *(const int4*)(g_cdst + p0);
    int e[4] = {ev.x, ev.y, ev.z, ev.w};
    int d[4] = {dv.x, dv.y, dv.z, dv.w};

    float a[4][16];
    #pragma unroll
    for (int q = 0; q < 4; q++) {
        const float4* ap = (const float4*)(ea + e[q]*16);
        #pragma unroll
        for (int r = 0; r < 4; r++) {
            float4 v = ap[r];
            a[q][4*r+0]=v.x; a[q][4*r+1]=v.y; a[q][4*r+2]=v.z; a[q][4*r+3]=v.w;
        }
    }

    #pragma unroll 1
    for (int l = 0; l < NL; l++) {
        const float* W = &sw[l*LSTRIDE];
        float b2 = W[288];
        float z[4] = {b2, b2, b2, b2};
        #pragma unroll
        for (int j = 0; j < 16; j++) {
            const float4* wc = (const float4*)&W[j*16];
            float4 w0 = wc[0], w1 = wc[1], w2 = wc[2], w3 = wc[3];
            float b1j = W[256+j];
            float w2j = W[272+j];
            #pragma unroll
            for (int q = 0; q < 4; q++) {
                float t = b1j;
                t=fmaf(a[q][0],w0.x,t);  t=fmaf(a[q][1],w0.y,t);
                t=fmaf(a[q][2],w0.z,t);  t=fmaf(a[q][3],w0.w,t);
                t=fmaf(a[q][4],w1.x,t);  t=fmaf(a[q][5],w1.y,t);
                t=fmaf(a[q][6],w1.z,t);  t=fmaf(a[q][7],w1.w,t);
                t=fmaf(a[q][8],w2.x,t);  t=fmaf(a[q][9],w2.y,t);
                t=fmaf(a[q][10],w2.z,t); t=fmaf(a[q][11],w2.w,t);
                t=fmaf(a[q][12],w3.x,t); t=fmaf(a[q][13],w3.y,t);
                t=fmaf(a[q][14],w3.z,t); t=fmaf(a[q][15],w3.w,t);
                t = fmaxf(t, 0.0f);
                z[q] = fmaf(t, w2j, z[q]);
            }
        }
        float4 ewv;
        ewv.x = 1.0f / (1.0f + __expf(-z[0]));
        ewv.y = 1.0f / (1.0f + __expf(-z[1]));
        ewv.z = 1.0f / (1.0f + __expf(-z[2]));
        ewv.w = 1.0f / (1.0f + __expf(-z[3]));
        *(float4*)(g_ew + l*NE + p0) = ewv;
        atomicAdd(&g_deg[d[0]*16 + l], ewv.x);
        atomicAdd(&g_deg[d[1]*16 + l], ewv.y);
        atomicAdd(&g_deg[d[2]*16 + l], ewv.z);
        atomicAdd(&g_deg[d[3]*16 + l], ewv.w);
    }
}

__global__ void k_rsqrt() {
    int i = blockIdx.x*blockDim.x + threadIdx.x;
    if (i < NN*16) g_deg[i] = rsqrtf(g_deg[i]);   // deg >= 1 always
}

__global__ void k_norm() {
    int p = blockIdx.x*256 + threadIdx.x;   // always < NE
    int s = g_csrc[p], d = g_cdst[p];
    float ds[16], dd[16];
    const float4* sp = (const float4*)(g_deg + s*16);
    const float4* dp = (const float4*)(g_deg + d*16);
    #pragma unroll
    for (int q = 0; q < 4; q++) {
        float4 v = sp[q]; ds[4*q]=v.x; ds[4*q+1]=v.y; ds[4*q+2]=v.z; ds[4*q+3]=v.w;
        float4 u = dp[q]; dd[4*q]=u.x; dd[4*q+1]=u.y; dd[4*q+2]=u.z; dd[4*q+3]=u.w;
    }
    #pragma unroll
    for (int l = 0; l < NL; l++)
        g_ew[l*NE + p] *= ds[l]*dd[l];
}

// ---------------- fused BN+ReLU+GEMM: 2 rows x 32 cols per thread ----------------
// block = 256 threads = 128 row-slots x 2 col-halves; covers 256 rows
__global__ __launch_bounds__(256) void k_gemm(
    const float* __restrict__ A, const float* __restrict__ W,
    __half* __restrict__ H, int slot)     // slot < 0 : no BN
{
    __shared__ __align__(16) float sW[64*64];   // k-major: sW[k*64+col]
    __shared__ float smu[64], ssc[64];
    int t = threadIdx.x;
    const float4* W4 = (const float4*)W;
    float4* sW4 = (float4*)sW;
    #pragma unroll
    for (int i = 0; i < 4; i++) sW4[t + i*256] = W4[t + i*256];
    if (slot >= 0 && t < 64) {
        double mu  = g_colsum[slot*64 + t] / (double)NN;
        double var = g_colsq[slot*64 + t] / (double)NN - mu*mu;
        if (var < 0.0) var = 0.0;
        smu[t] = (float)mu;
        ssc[t] = (float)(1.0 / sqrt(var + 1e-5));
    }
    __syncthreads();

    int cg = t >> 7;            // col half: 0 or 1
    int i  = t & 127;           // row slot
    int r0 = blockIdx.x*256 + i;
    int r1 = r0 + 128;
    if (r0 >= NN) return;
    bool v1 = (r1 < NN);
    const float4* A0 = (const float4*)(A + r0*64);
    const float4* A1 = (const float4*)(A + (v1 ? r1 : r0)*64);
    const int cbase = cg*32;

    float acc0[32], acc1[32];
    #pragma unroll
    for (int j = 0; j < 32; j++) { acc0[j] = 0.0f; acc1[j] = 0.0f; }

    #pragma unroll 2
    for (int g = 0; g < 16; g++) {
        float4 a0 = A0[g];
        float4 a1 = A1[g];
        if (slot >= 0) {
            a0.x = fmaxf((a0.x - smu[4*g+0]) * ssc[4*g+0], 0.0f);
            a0.y = fmaxf((a0.y - smu[4*g+1]) * ssc[4*g+1], 0.0f);
            a0.z = fmaxf((a0.z - smu[4*g+2]) * ssc[4*g+2], 0.0f);
            a0.w = fmaxf((a0.w - smu[4*g+3]) * ssc[4*g+3], 0.0f);
            a1.x = fmaxf((a1.x - smu[4*g+0]) * ssc[4*g+0], 0.0f);
            a1.y = fmaxf((a1.y - smu[4*g+1]) * ssc[4*g+1], 0.0f);
            a1.z = fmaxf((a1.z - smu[4*g+2]) * ssc[4*g+2], 0.0f);
            a1.w = fmaxf((a1.w - smu[4*g+3]) * ssc[4*g+3], 0.0f);
        }
        float av0[4] = {a0.x, a0.y, a0.z, a0.w};
        float av1[4] = {a1.x, a1.y, a1.z, a1.w};
        #pragma unroll
        for (int kk = 0; kk < 4; kk++) {
            const float4* wr = (const float4*)&sW[(4*g+kk)*64 + cbase];
            float b0 = av0[kk], b1 = av1[kk];
            #pragma unroll
            for (int j = 0; j < 8; j++) {
                float4 w = wr[j];
                acc0[4*j+0] = fmaf(b0, w.x, acc0[4*j+0]);
                acc0[4*j+1] = fmaf(b0, w.y, acc0[4*j+1]);
                acc0[4*j+2] = fmaf(b0, w.z, acc0[4*j+2]);
                acc0[4*j+3] = fmaf(b0, w.w, acc0[4*j+3]);
                acc1[4*j+0] = fmaf(b1, w.x, acc1[4*j+0]);
                acc1[4*j+1] = fmaf(b1, w.y, acc1[4*j+1]);
                acc1[4*j+2] = fmaf(b1, w.z, acc1[4*j+2]);
                acc1[4*j+3] = fmaf(b1, w.w, acc1[4*j+3]);
            }
        }
    }
    // pack to fp16: 32 cols = 64B = 4x uint4 per row
    uint4* H0 = (uint4*)(H + r0*64 + cbase);
    #pragma unroll
    for (int j = 0; j < 4; j++) {
        union { __half2 h2[4]; uint4 u; } pk;
        pk.h2[0] = __floats2half2_rn(acc0[8*j+0], acc0[8*j+1]);
        pk.h2[1] = __floats2half2_rn(acc0[8*j+2], acc0[8*j+3]);
        pk.h2[2] = __floats2half2_rn(acc0[8*j+4], acc0[8*j+5]);
        pk.h2[3] = __floats2half2_rn(acc0[8*j+6], acc0[8*j+7]);
        H0[j] = pk.u;
    }
    if (v1) {
        uint4* H1 = (uint4*)(H + r1*64 + cbase);
        #pragma unroll
        for (int j = 0; j < 4; j++) {
            union { __half2 h2[4]; uint4 u; } pk;
            pk.h2[0] = __floats2half2_rn(acc1[8*j+0], acc1[8*j+1]);
            pk.h2[1] = __floats2half2_rn(acc1[8*j+2], acc1[8*j+3]);
            pk.h2[2] = __floats2half2_rn(acc1[8*j+4], acc1[8*j+5]);
            pk.h2[3] = __floats2half2_rn(acc1[8*j+6], acc1[8*j+7]);
            H1[j] = pk.u;
        }
    }
}

// ---------------- BN statistics (fp32 per-thread accumulation, fp64 reduce) ----------------
__global__ void k_bnstats(const float* __restrict__ A, int slot) {
    int t = threadIdx.x;
    int c = t & 63, rg = t >> 6;              // 256 threads: 4 row lanes x 64 cols
    float s = 0.0f, q = 0.0f;                 // ~49 elements per thread: fp32 is exact enough
    for (int r = blockIdx.x*4 + rg; r < NN; r += gridDim.x*4) {
        float v = A[r*64 + c];
        s += v; q = fmaf(v, v, q);
    }
    __shared__ float ss[256], sq[256];
    ss[t] = s; sq[t] = q; __syncthreads();
    if (t < 64) {
        double S = (double)ss[t] + (double)ss[t+64] + (double)ss[t+128] + (double)ss[t+192];
        double Q = (double)sq[t] + (double)sq[t+64] + (double)sq[t+128] + (double)sq[t+192];
        atomicAdd(&g_colsum[slot*64 + c], S);
        atomicAdd(&g_colsq [slot*64 + c], Q);
    }
}

// ---------------- CSR aggregation (fp16 gathers, fp32 accumulate) + epilogues ----------------
__global__ __launch_bounds__(256) void k_agg(
    const __half* __restrict__ h, const float* __restrict__ nrm,
    int layer, const float* __restrict__ bias,
    float* __restrict__ cur, float* __restrict__ acc,
    const int* __restrict__ batch, int mode)
{
    int t = threadIdx.x;
    int w = (blockIdx.x*256 + t) >> 5;
    int lane = t & 31;
    if (w >= NN) return;
    int c = lane*2;
    float dv = g_deg[w*16 + layer];
    float selfw = dv*dv;
    float2 hv = __half22float2(*(const __half2*)(h + w*64 + c));
    float ax = fmaf(selfw, hv.x, bias[c]);
    float ay = fmaf(selfw, hv.y, bias[c+1]);
    int p0 = g_rowptr[w], p1 = g_rowptr[w+1];
    int p = p0;
    for (; p + 3 < p1; p += 4) {
        int s0 = g_csrc[p],   s1 = g_csrc[p+1];
        int s2 = g_csrc[p+2], s3 = g_csrc[p+3];
        float w0 = nrm[p],   w1 = nrm[p+1];
        float w2 = nrm[p+2], w3 = nrm[p+3];
        float2 v0 = __half22float2(*(const __half2*)(h + s0*64 + c));
        float2 v1 = __half22float2(*(const __half2*)(h + s1*64 + c));
        float2 v2 = __half22float2(*(const __half2*)(h + s2*64 + c));
        float2 v3 = __half22float2(*(const __half2*)(h + s3*64 + c));
        ax = fmaf(w0, v0.x, ax); ay = fmaf(w0, v0.y, ay);
        ax = fmaf(w1, v1.x, ax); ay = fmaf(w1, v1.y, ay);
        ax = fmaf(w2, v2.x, ax); ay = fmaf(w2, v2.y, ay);
        ax = fmaf(w3, v3.x, ax); ay = fmaf(w3, v3.y, ay);
    }
    for (; p < p1; p++) {
        int s = g_csrc[p];
        float wt = nrm[p];
        float2 v = __half22float2(*(const __half2*)(h + s*64 + c));
        ax = fmaf(wt, v.x, ax);
        ay = fmaf(wt, v.y, ay);
    }
    if (mode & M_SKIP) {
        float2 a2 = *(float2*)(acc + w*64 + c);
        ax += a2.x; ay += a2.y;
        a2.x += ax; a2.y += ay;
        *(float2*)(acc + w*64 + c) = a2;
    }
    float2 o; o.x = ax; o.y = ay;
    *(float2*)(cur + w*64 + c) = o;
    if (mode & M_COPY) *(float2*)(acc + w*64 + c) = o;
    if (mode & M_POOL) {
        float rx = fmaxf(ax, 0.0f), ry = fmaxf(ay, 0.0f);
        int b = batch[w];
        atomicMax((int*)&g_pool[b*64 + c],     __float_as_int(rx));
        atomicMax((int*)&g_pool[b*64 + c + 1], __float_as_int(ry));
    }
}

// ---------------- readout ----------------
__global__ void k_final(const float* __restrict__ linW, const float* __restrict__ linb,
                        float* __restrict__ out) {
    int g = blockIdx.x*blockDim.x + threadIdx.x;
    if (g >= NG) return;
    float a0 = linb[0], a1 = linb[1];
    #pragma unroll 8
    for (int c = 0; c < CC; c++) {
        float v = g_pool[g*64 + c];
        a0 = fmaf(v, linW[c*2+0], a0);
        a1 = fmaf(v, linW[c*2+1], a1);
    }
    out[g*2+0] = a0;
    out[g*2+1] = a1;
}

// ---------------- launch ----------------
extern "C" void kernel_launch(void* const* d_in, const int* in_sizes, int n_in,
                              void* d_out, int out_size)
{
    const float* x     = (const float*)d_in[0];
    const int*   ei    = (const int*)  d_in[1];
    const int*   batch = (const int*)  d_in[2];
    /* d_in[3] = dropout (unused, eval mode) */
    const float* ea    = (const float*)d_in[4];
    const float* Wlin1 = (const float*)d_in[5];
    const float* bias1 = (const float*)d_in[6];
    const float* m1W1  = (const float*)d_in[7];
    const float* m1b1  = (const float*)d_in[8];
    const float* m2W1  = (const float*)d_in[9];
    const float* m2b1  = (const float*)d_in[10];
    const float* hWlin = (const float*)d_in[11];
    const float* hbias = (const float*)d_in[12];
    const float* hm1W  = (const float*)d_in[13];
    const float* hm1b  = (const float*)d_in[14];
    const float* hm2W  = (const float*)d_in[15];
    const float* hm2b  = (const float*)d_in[16];
    const float* linW  = (const float*)d_in[17];
    const float* linb  = (const float*)d_in[18];
    float* out = (float*)d_out;

    const int* src = ei;
    const int* dst = ei + NE;

    __half *p_h;
    float *p_cur, *p_acc, *p_ew;
    cudaGetSymbolAddress((void**)&p_h,   g_h);
    cudaGetSymbolAddress((void**)&p_cur, g_cur);
    cudaGetSymbolAddress((void**)&p_acc, g_acc);
    cudaGetSymbolAddress((void**)&p_ew,  g_ew);

    const int EB = NE / 256;                  // 3125 (exact)
    const int MB = (NE/4 + 255) / 256;        // 782 (edgemlp, 4 edges/thread)
    const int GB = (NN + 255) / 256;          // 196 (gemm, 256 rows/block)
    const int AB = (NN*32) / 256;             // 6250 (exact)

    // prologue: CSR + all edge norms for all 13 layers
    k_reset  <<<(NN*16 + 255)/256, 256>>>();
    k_hist   <<<EB, 256>>>(dst);
    k_scanall<<<1, 1024>>>();
    k_scatter<<<EB, 256>>>(src, dst);
    k_edgemlp<<<MB, 256>>>(ea, m1W1, m1b1, m2W1, m2b1, hm1W, hm1b, hm2W, hm2b);
    k_rsqrt  <<<(NN*16 + 255)/256, 256>>>();
    k_norm   <<<EB, 256>>>();

    // conv1
    k_gemm<<<GB, 256>>>(x, Wlin1, p_h, -1);
    k_agg <<<AB, 256>>>(p_h, p_ew, 0, bias1, p_cur, p_acc, batch, M_COPY);

    // 12 hidden convs (6 blocks x 2)
    for (int j = 0; j < 12; j++) {
        int l = j + 1;
        k_bnstats<<<256, 256>>>(p_cur, j);
        k_gemm<<<GB, 256>>>(p_cur, hWlin + j*CC*CC, p_h, j);
        int mode;
        if (j == 11)      mode = M_SKIP | M_POOL;   // last: skip + relu + pool
        else if (j & 1)   mode = M_SKIP;            // end of block: dense skip
        else              mode = 0;
        k_agg <<<AB, 256>>>(p_h, p_ew + l*NE, l, hbias + j*CC, p_cur, p_acc, batch, mode);
    }

    k_final<<<(NG + 63)/64, 64>>>(linW, linb, out);
}

// round 7
// speedup vs baseline: 1.4402x; 1.0805x over previous
#include <cuda_runtime.h>
#include <cuda_fp16.h>
#include <mma.h>
#include <math.h>

using namespace nvcuda;

#define NN 50000
#define NE 800000
#define NG 500
#define CC 64
#define NL 13          // 1 + 12 PDN convs
#define LSTRIDE 292    // per-layer smem stride (half2 entries) for edge MLP weights

// modes for k_agg epilogue
#define M_COPY  1
#define M_SKIP  2
#define M_POOL  8

// ---------------- scratch (device globals; no allocation) ----------------
__device__ __half g_h  [NN*CC];     // fp16 GEMM output (gather bandwidth halved)
__device__ float  g_cur[NN*CC];
__device__ float  g_acc[NN*CC];
__device__ float  g_ew [NL*NE];     // raw ew (CSR order) -> scaled to norm in k_norm
__device__ float  g_deg[NN*16];     // [node][16] deg -> rsqrt(deg) in place
__device__ int    g_cnt[NN];
__device__ int    g_rowptr[NN+1];
__device__ int    g_cursor[NN];
__device__ int    g_eid [NE];
__device__ int    g_csrc[NE];
__device__ int    g_cdst[NE];
__device__ double g_colsum[13*64];
__device__ double g_colsq [13*64];
__device__ float  g_pool[NG*CC];

// ---------------- init ----------------
__global__ void k_reset() {
    int i = blockIdx.x*blockDim.x + threadIdx.x;
    if (i < NN*16) g_deg[i] = 1.0f;          // deg starts at self-loop weight 1
    if (i < NN)    g_cnt[i] = 0;
    if (i < NG*CC) g_pool[i] = 0.0f;
    if (i < 13*64) { g_colsum[i] = 0.0; g_colsq[i] = 0.0; }
}

// ---------------- CSR build ----------------
__global__ void k_hist(const int* __restrict__ dst) {
    int e = blockIdx.x*blockDim.x + threadIdx.x;
    if (e < NE) atomicAdd(&g_cnt[dst[e]], 1);
}

// single-block chunked scan: 1024 threads, 49 chunks
__global__ void k_scanall() {
    __shared__ int wsum[32];
    int t = threadIdx.x;
    int lane = t & 31, wid = t >> 5;
    int carry = 0;
    for (int base = 0; base < NN; base += 1024) {
        int i = base + t;
        int v = (i < NN) ? g_cnt[i] : 0;
        int x = v;
        #pragma unroll
        for (int off = 1; off < 32; off <<= 1) {
            int u = __shfl_up_sync(0xffffffffu, x, off);
            if (lane >= off) x += u;
        }
        if (lane == 31) wsum[wid] = x;
        __syncthreads();
        if (wid == 0) {
            int y = wsum[lane];
            #pragma unroll
            for (int off = 1; off < 32; off <<= 1) {
                int u = __shfl_up_sync(0xffffffffu, y, off);
                if (lane >= off) y += u;
            }
            wsum[lane] = y;
        }
        __syncthreads();
        int pre = (wid > 0) ? wsum[wid-1] : 0;
        int excl = carry + pre + x - v;
        if (i < NN) { g_rowptr[i] = excl; g_cursor[i] = excl; }
        int tot = wsum[31];
        __syncthreads();
        carry += tot;
    }
    if (t == 0) g_rowptr[NN] = carry;
}

__global__ void k_scatter(const int* __restrict__ src, const int* __restrict__ dst) {
    int e = blockIdx.x*blockDim.x + threadIdx.x;
    if (e >= NE) return;
    int d = dst[e];
    int p = atomicAdd(&g_cursor[d], 1);
    g_eid[p]  = e;
    g_csrc[p] = src[e];
    g_cdst[p] = d;
}

// ---------------- edge MLPs: half2, 4 edges/thread (2 per half2 lane), all 13 layers ----------------
__global__ __launch_bounds__(256) void k_edgemlp(
    const float* __restrict__ ea,
    const float* __restrict__ m1W, const float* __restrict__ m1b,
    const float* __restrict__ m2W, const float* __restrict__ m2b,
    const float* __restrict__ hm1W, const float* __restrict__ hm1b,
    const float* __restrict__ hm2W, const float* __restrict__ hm2b)
{
    __shared__ __align__(16) __half2 sw[NL*LSTRIDE];
    // per layer l at sw+l*LSTRIDE (each entry = {w,w}):
    //   [0..255] W1^T (W1T[j*16+i]=W1[i][j]), [256..271] b1, [272..287] W2, [288] b2
    for (int idx = threadIdx.x; idx < NL*LSTRIDE; idx += 256) {
        int l = idx / LSTRIDE, r = idx - l*LSTRIDE;
        float v = 0.0f;
        if (r < 256) {
            int j = r >> 4, i = r & 15;
            v = (l == 0) ? m1W[i*16 + j] : hm1W[(l-1)*256 + i*16 + j];
        } else if (r < 272) {
            v = (l == 0) ? m1b[r-256] : hm1b[(l-1)*16 + (r-256)];
        } else if (r < 288) {
            v = (l == 0) ? m2W[r-272] : hm2W[(l-1)*16 + (r-272)];
        } else if (r == 288) {
            v = (l == 0) ? m2b[0] : hm2b[l-1];
        }
        sw[idx] = __half2half2(__float2half(v));
    }
    __syncthreads();

    int tid = blockIdx.x*256 + threadIdx.x;
    if (tid >= NE/4) return;
    int p0 = tid*4;

    int4 ev = *(const int4*)(g_eid  + p0);
    int4 dv = *(const int4*)(g_cdst + p0);
    int e[4] = {ev.x, ev.y, ev.z, ev.w};
    int d[4] = {dv.x, dv.y, dv.z, dv.w};

    // a2[p][i] = {feat_i of edge 2p, feat_i of edge 2p+1}
    __half2 a2[2][16];
    {
        float a[4][16];
        #pragma unroll
        for (int q = 0; q < 4; q++) {
            const float4* ap = (const float4*)(ea + e[q]*16);
            #pragma unroll
            for (int r = 0; r < 4; r++) {
                float4 v = ap[r];
                a[q][4*r+0]=v.x; a[q][4*r+1]=v.y; a[q][4*r+2]=v.z; a[q][4*r+3]=v.w;
            }
        }
        #pragma unroll
        for (int i = 0; i < 16; i++) {
            a2[0][i] = __floats2half2_rn(a[0][i], a[1][i]);
            a2[1][i] = __floats2half2_rn(a[2][i], a[3][i]);
        }
    }

    const __half2 zero2 = __float2half2_rn(0.0f);

    #pragma unroll 1
    for (int l = 0; l < NL; l++) {
        const __half2* W = &sw[l*LSTRIDE];
        __half2 b2v = W[288];
        __half2 z0 = b2v, z1 = b2v;
        #pragma unroll
        for (int j = 0; j < 16; j++) {
            const __half2* wc = &W[j*16];
            __half2 b1j = W[256+j];
            __half2 w2j = W[272+j];
            __half2 t0 = b1j, t1 = b1j;
            #pragma unroll
            for (int i = 0; i < 16; i++) {
                __half2 w = wc[i];
                t0 = __hfma2(a2[0][i], w, t0);
                t1 = __hfma2(a2[1][i], w, t1);
            }
            t0 = __hmax2(t0, zero2);
            t1 = __hmax2(t1, zero2);
            z0 = __hfma2(t0, w2j, z0);
            z1 = __hfma2(t1, w2j, z1);
        }
        float2 f0 = __half22float2(z0);
        float2 f1 = __half22float2(z1);
        float4 ewv;
        ewv.x = 1.0f / (1.0f + __expf(-f0.x));
        ewv.y = 1.0f / (1.0f + __expf(-f0.y));
        ewv.z = 1.0f / (1.0f + __expf(-f1.x));
        ewv.w = 1.0f / (1.0f + __expf(-f1.y));
        *(float4*)(g_ew + l*NE + p0) = ewv;
        atomicAdd(&g_deg[d[0]*16 + l], ewv.x);
        atomicAdd(&g_deg[d[1]*16 + l], ewv.y);
        atomicAdd(&g_deg[d[2]*16 + l], ewv.z);
        atomicAdd(&g_deg[d[3]*16 + l], ewv.w);
    }
}

__global__ void k_rsqrt() {
    int i = blockIdx.x*blockDim.x + threadIdx.x;
    if (i < NN*16) g_deg[i] = rsqrtf(g_deg[i]);   // deg >= 1 always
}

__global__ void k_norm() {
    int p = blockIdx.x*256 + threadIdx.x;   // always < NE
    int s = g_csrc[p], d = g_cdst[p];
    float ds[16], dd[16];
    const float4* sp = (const float4*)(g_deg + s*16);
    const float4* dp = (const float4*)(g_deg + d*16);
    #pragma unroll
    for (int q = 0; q < 4; q++) {
        float4 v = sp[q]; ds[4*q]=v.x; ds[4*q+1]=v.y; ds[4*q+2]=v.z; ds[4*q+3]=v.w;
        float4 u = dp[q]; dd[4*q]=u.x; dd[4*q+1]=u.y; dd[4*q+2]=u.z; dd[4*q+3]=u.w;
    }
    #pragma unroll
    for (int l = 0; l < NL; l++)
        g_ew[l*NE + p] *= ds[l]*dd[l];
}

// ---------------- fused BN+ReLU + tensor-core GEMM (wmma m16n16k16) ----------------
// block = 256 threads (8 warps), 128 rows; each warp: 16 rows x 64 cols
__global__ __launch_bounds__(256) void k_gemm(
    const float* __restrict__ A, const float* __restrict__ W,
    __half* __restrict__ H, int slot)     // slot < 0 : no BN
{
    __shared__ __align__(32) __half sA[128*64];   // 16 KB, fp16 BN-relu'd A tile
    __shared__ __align__(32) __half sW[64*64];    // 8 KB,  fp16 weights (k-major [k][n])
    __shared__ __align__(32) float  sC[8][16*64]; // 32 KB, per-warp fp32 C staging
    __shared__ float smu[64], ssc[64];

    int t = threadIdx.x;
    int base = blockIdx.x*128;

    if (slot >= 0 && t < 64) {
        double mu  = g_colsum[slot*64 + t] / (double)NN;
        double var = g_colsq[slot*64 + t] / (double)NN - mu*mu;
        if (var < 0.0) var = 0.0;
        smu[t] = (float)mu;
        ssc[t] = (float)(1.0 / sqrt(var + 1e-5));
    }
    // weights -> fp16 smem (no dependence on smu)
    for (int i = t; i < 4096; i += 256)
        sW[i] = __float2half(W[i]);
    __syncthreads();   // smu ready for A staging

    // stage A tile: BN+ReLU+fp16 (coalesced: consecutive threads = consecutive cols)
    if (slot >= 0) {
        for (int idx = t; idx < 8192; idx += 256) {
            int r = idx >> 6, c = idx & 63;
            float v = (base + r < NN) ? A[(size_t)(base + r)*64 + c] : 0.0f;
            v = fmaxf((v - smu[c]) * ssc[c], 0.0f);
            sA[idx] = __float2half(v);
        }
    } else {
        for (int idx = t; idx < 8192; idx += 256) {
            int r = idx >> 6;
            float v = (base + r < NN) ? A[(size_t)(base + r)*64 + (idx & 63)] : 0.0f;
            sA[idx] = __float2half(v);
        }
    }
    __syncthreads();

    int w = t >> 5;
    int lane = t & 31;

    wmma::fragment<wmma::accumulator, 16, 16, 16, float> acc[4];
    #pragma unroll
    for (int n = 0; n < 4; n++) wmma::fill_fragment(acc[n], 0.0f);

    #pragma unroll
    for (int k = 0; k < 4; k++) {
        wmma::fragment<wmma::matrix_a, 16, 16, 16, __half, wmma::row_major> af;
        wmma::load_matrix_sync(af, sA + (w*16)*64 + k*16, 64);
        #pragma unroll
        for (int n = 0; n < 4; n++) {
            wmma::fragment<wmma::matrix_b, 16, 16, 16, __half, wmma::row_major> bf;
            wmma::load_matrix_sync(bf, sW + (k*16)*64 + n*16, 64);
            wmma::mma_sync(acc[n], af, bf, acc[n]);
        }
    }

    // stage fp32 -> smem (per-warp private region), then fp16 coalesced store
    #pragma unroll
    for (int n = 0; n < 4; n++)
        wmma::store_matrix_sync(&sC[w][n*16], acc[n], 64, wmma::mem_row_major);

    int wrow = base + w*16;
    if (wrow < NN) {   // NN % 16 == 0, so warp tiles are all-or-nothing
        __half2* H2 = (__half2*)(H + (size_t)wrow*64);
        #pragma unroll
        for (int i = lane; i < 512; i += 32) {
            float x0 = sC[w][2*i], x1 = sC[w][2*i+1];
            H2[i] = __floats2half2_rn(x0, x1);
        }
    }
}

// ---------------- BN statistics (fp32 per-thread accumulation, fp64 reduce) ----------------
__global__ void k_bnstats(const float* __restrict__ A, int slot) {
    int t = threadIdx.x;
    int c = t & 63, rg = t >> 6;              // 256 threads: 4 row lanes x 64 cols
    float s = 0.0f, q = 0.0f;                 // ~49 elements per thread: fp32 is exact enough
    for (int r = blockIdx.x*4 + rg; r < NN; r += gridDim.x*4) {
        float v = A[r*64 + c];
        s += v; q = fmaf(v, v, q);
    }
    __shared__ float ss[256], sq[256];
    ss[t] = s; sq[t] = q; __syncthreads();
    if (t < 64) {
        double S = (double)ss[t] + (double)ss[t+64] + (double)ss[t+128] + (double)ss[t+192];
        double Q = (double)sq[t] + (double)sq[t+64] + (double)sq[t+128] + (double)sq[t+192];
        atomicAdd(&g_colsum[slot*64 + c], S);
        atomicAdd(&g_colsq [slot*64 + c], Q);
    }
}

// ---------------- CSR aggregation (fp16 gathers, fp32 accumulate) + epilogues ----------------
__global__ __launch_bounds__(256) void k_agg(
    const __half* __restrict__ h, const float* __restrict__ nrm,
    int layer, const float* __restrict__ bias,
    float* __restrict__ cur, float* __restrict__ acc,
    const int* __restrict__ batch, int mode)
{
    int t = threadIdx.x;
    int w = (blockIdx.x*256 + t) >> 5;
    int lane = t & 31;
    if (w >= NN) return;
    int c = lane*2;
    float dv = g_deg[w*16 + layer];
    float selfw = dv*dv;
    float2 hv = __half22float2(*(const __half2*)(h + w*64 + c));
    float ax = fmaf(selfw, hv.x, bias[c]);
    float ay = fmaf(selfw, hv.y, bias[c+1]);
    int p0 = g_rowptr[w], p1 = g_rowptr[w+1];
    int p = p0;
    for (; p + 3 < p1; p += 4) {
        int s0 = g_csrc[p],   s1 = g_csrc[p+1];
        int s2 = g_csrc[p+2], s3 = g_csrc[p+3];
        float w0 = nrm[p],   w1 = nrm[p+1];
        float w2 = nrm[p+2], w3 = nrm[p+3];
        float2 v0 = __half22float2(*(const __half2*)(h + s0*64 + c));
        float2 v1 = __half22float2(*(const __half2*)(h + s1*64 + c));
        float2 v2 = __half22float2(*(const __half2*)(h + s2*64 + c));
        float2 v3 = __half22float2(*(const __half2*)(h + s3*64 + c));
        ax = fmaf(w0, v0.x, ax); ay = fmaf(w0, v0.y, ay);
        ax = fmaf(w1, v1.x, ax); ay = fmaf(w1, v1.y, ay);
        ax = fmaf(w2, v2.x, ax); ay = fmaf(w2, v2.y, ay);
        ax = fmaf(w3, v3.x, ax); ay = fmaf(w3, v3.y, ay);
    }
    for (; p < p1; p++) {
        int s = g_csrc[p];
        float wt = nrm[p];
        float2 v = __half22float2(*(const __half2*)(h + s*64 + c));
        ax = fmaf(wt, v.x, ax);
        ay = fmaf(wt, v.y, ay);
    }
    if (mode & M_SKIP) {
        float2 a2 = *(float2*)(acc + w*64 + c);
        ax += a2.x; ay += a2.y;
        a2.x += ax; a2.y += ay;
        *(float2*)(acc + w*64 + c) = a2;
    }
    float2 o; o.x = ax; o.y = ay;
    *(float2*)(cur + w*64 + c) = o;
    if (mode & M_COPY) *(float2*)(acc + w*64 + c) = o;
    if (mode & M_POOL) {
        float rx = fmaxf(ax, 0.0f), ry = fmaxf(ay, 0.0f);
        int b = batch[w];
        atomicMax((int*)&g_pool[b*64 + c],     __float_as_int(rx));
        atomicMax((int*)&g_pool[b*64 + c + 1], __float_as_int(ry));
    }
}

// ---------------- readout ----------------
__global__ void k_final(const float* __restrict__ linW, const float* __restrict__ linb,
                        float* __restrict__ out) {
    int g = blockIdx.x*blockDim.x + threadIdx.x;
    if (g >= NG) return;
    float a0 = linb[0], a1 = linb[1];
    #pragma unroll 8
    for (int c = 0; c < CC; c++) {
        float v = g_pool[g*64 + c];
        a0 = fmaf(v, linW[c*2+0], a0);
        a1 = fmaf(v, linW[c*2+1], a1);
    }
    out[g*2+0] = a0;
    out[g*2+1] = a1;
}

// ---------------- launch ----------------
extern "C" void kernel_launch(void* const* d_in, const int* in_sizes, int n_in,
                              void* d_out, int out_size)
{
    const float* x     = (const float*)d_in[0];
    const int*   ei    = (const int*)  d_in[1];
    const int*   batch = (const int*)  d_in[2];
    /* d_in[3] = dropout (unused, eval mode) */
    const float* ea    = (const float*)d_in[4];
    const float* Wlin1 = (const float*)d_in[5];
    const float* bias1 = (const float*)d_in[6];
    const float* m1W1  = (const float*)d_in[7];
    const float* m1b1  = (const float*)d_in[8];
    const float* m2W1  = (const float*)d_in[9];
    const float* m2b1  = (const float*)d_in[10];
    const float* hWlin = (const float*)d_in[11];
    const float* hbias = (const float*)d_in[12];
    const float* hm1W  = (const float*)d_in[13];
    const float* hm1b  = (const float*)d_in[14];
    const float* hm2W  = (const float*)d_in[15];
    const float* hm2b  = (const float*)d_in[16];
    const float* linW  = (const float*)d_in[17];
    const float* linb  = (const float*)d_in[18];
    float* out = (float*)d_out;

    const int* src = ei;
    const int* dst = ei + NE;

    __half *p_h;
    float *p_cur, *p_acc, *p_ew;
    cudaGetSymbolAddress((void**)&p_h,   g_h);
    cudaGetSymbolAddress((void**)&p_cur, g_cur);
    cudaGetSymbolAddress((void**)&p_acc, g_acc);
    cudaGetSymbolAddress((void**)&p_ew,  g_ew);

    const int EB = NE / 256;                  // 3125 (exact)
    const int MB = (NE/4 + 255) / 256;        // 782 (edgemlp, 4 edges/thread)
    const int GB = (NN + 127) / 128;          // 391 (gemm, 128 rows/block)
    const int AB = (NN*32) / 256;             // 6250 (exact)

    // prologue: CSR + all edge norms for all 13 layers
    k_reset  <<<(NN*16 + 255)/256, 256>>>();
    k_hist   <<<EB, 256>>>(dst);
    k_scanall<<<1, 1024>>>();
    k_scatter<<<EB, 256>>>(src, dst);
    k_edgemlp<<<MB, 256>>>(ea, m1W1, m1b1, m2W1, m2b1, hm1W, hm1b, hm2W, hm2b);
    k_rsqrt  <<<(NN*16 + 255)/256, 256>>>();
    k_norm   <<<EB, 256>>>();

    // conv1
    k_gemm<<<GB, 256>>>(x, Wlin1, p_h, -1);
    k_agg <<<AB, 256>>>(p_h, p_ew, 0, bias1, p_cur, p_acc, batch, M_COPY);

    // 12 hidden convs (6 blocks x 2)
    for (int j = 0; j < 12; j++) {
        int l = j + 1;
        k_bnstats<<<256, 256>>>(p_cur, j);
        k_gemm<<<GB, 256>>>(p_cur, hWlin + j*CC*CC, p_h, j);
        int mode;
        if (j == 11)      mode = M_SKIP | M_POOL;   // last: skip + relu + pool
        else if (j & 1)   mode = M_SKIP;            // end of block: dense skip
        else              mode = 0;
        k_agg <<<AB, 256>>>(p_h, p_ew + l*NE, l, hbias + j*CC, p_cur, p_acc, batch, mode);
    }

    k_final<<<(NG + 63)/64, 64>>>(linW, linb, out);
}

// round 10
// speedup vs baseline: 1.4672x; 1.0187x over previous
#include <cuda_runtime.h>
#include <cuda_fp16.h>
#include <mma.h>
#include <math.h>

using namespace nvcuda;

#define NN 50000
#define NE 800000
#define NG 500
#define CC 64
#define NL 13          // 1 + 12 PDN convs
#define LSTRIDE 292    // per-layer smem stride (half2 entries) for edge MLP weights

// modes for k_agg epilogue
#define M_COPY  1
#define M_SKIP  2
#define M_POOL  8

// ---------------- scratch (device globals; no allocation) ----------------
__device__ __half g_h  [NN*CC];     // fp16 GEMM output (gather bandwidth halved)
__device__ float  g_cur[NN*CC];
__device__ float  g_acc[NN*CC];
__device__ float  g_ew [NL*NE];     // raw ew (CSR order) -> scaled to ew*dis_src in k_norm
__device__ float  g_deg[NN*16];     // [node][16] deg -> rsqrt(deg) in place (k_rsqrt)
__device__ int    g_cnt[NN];
__device__ int    g_rowptr[NN+1];
__device__ int    g_cursor[NN];
__device__ __align__(16) int2 g_epack[NE];   // {eid, dst} in CSR order
__device__ int    g_csrc[NE];
__device__ double g_colsum[13*64];
__device__ double g_colsq [13*64];
__device__ float  g_pool[NG*CC];

// ---------------- init ----------------
__global__ void k_reset() {
    int i = blockIdx.x*blockDim.x + threadIdx.x;
    if (i < NN*16) g_deg[i] = 1.0f;          // deg starts at self-loop weight 1
    if (i < NN)    g_cnt[i] = 0;
    if (i < NG*CC) g_pool[i] = 0.0f;
    if (i < 13*64) { g_colsum[i] = 0.0; g_colsq[i] = 0.0; }
}

// ---------------- CSR build ----------------
__global__ void k_hist(const int* __restrict__ dst) {
    int e = blockIdx.x*blockDim.x + threadIdx.x;
    if (e < NE) atomicAdd(&g_cnt[dst[e]], 1);
}

// single-block chunked scan: 1024 threads, 49 chunks
__global__ void k_scanall() {
    __shared__ int wsum[32];
    int t = threadIdx.x;
    int lane = t & 31, wid = t >> 5;
    int carry = 0;
    for (int base = 0; base < NN; base += 1024) {
        int i = base + t;
        int v = (i < NN) ? g_cnt[i] : 0;
        int x = v;
        #pragma unroll
        for (int off = 1; off < 32; off <<= 1) {
            int u = __shfl_up_sync(0xffffffffu, x, off);
            if (lane >= off) x += u;
        }
        if (lane == 31) wsum[wid] = x;
        __syncthreads();
        if (wid == 0) {
            int y = wsum[lane];
            #pragma unroll
            for (int off = 1; off < 32; off <<= 1) {
                int u = __shfl_up_sync(0xffffffffu, y, off);
                if (lane >= off) y += u;
            }
            wsum[lane] = y;
        }
        __syncthreads();
        int pre = (wid > 0) ? wsum[wid-1] : 0;
        int excl = carry + pre + x - v;
        if (i < NN) { g_rowptr[i] = excl; g_cursor[i] = excl; }
        int tot = wsum[31];
        __syncthreads();
        carry += tot;
    }
    if (t == 0) g_rowptr[NN] = carry;
}

__global__ void k_scatter(const int* __restrict__ src, const int* __restrict__ dst) {
    int e = blockIdx.x*blockDim.x + threadIdx.x;
    if (e >= NE) return;
    int d = dst[e];
    int p = atomicAdd(&g_cursor[d], 1);
    int2 pk; pk.x = e; pk.y = d;
    g_epack[p] = pk;
    g_csrc[p]  = src[e];
}

// ---------------- edge MLPs: half2, 4 edges/thread (2 per half2 lane), all 13 layers ----------------
__global__ __launch_bounds__(256) void k_edgemlp(
    const float* __restrict__ ea,
    const float* __restrict__ m1W, const float* __restrict__ m1b,
    const float* __restrict__ m2W, const float* __restrict__ m2b,
    const float* __restrict__ hm1W, const float* __restrict__ hm1b,
    const float* __restrict__ hm2W, const float* __restrict__ hm2b)
{
    __shared__ __align__(16) __half2 sw[NL*LSTRIDE];
    // per layer l at sw+l*LSTRIDE (each entry = {w,w}):
    //   [0..255] W1^T (W1T[j*16+i]=W1[i][j]), [256..271] b1, [272..287] W2, [288] b2
    for (int idx = threadIdx.x; idx < NL*LSTRIDE; idx += 256) {
        int l = idx / LSTRIDE, r = idx - l*LSTRIDE;
        float v = 0.0f;
        if (r < 256) {
            int j = r >> 4, i = r & 15;
            v = (l == 0) ? m1W[i*16 + j] : hm1W[(l-1)*256 + i*16 + j];
        } else if (r < 272) {
            v = (l == 0) ? m1b[r-256] : hm1b[(l-1)*16 + (r-256)];
        } else if (r < 288) {
            v = (l == 0) ? m2W[r-272] : hm2W[(l-1)*16 + (r-272)];
        } else if (r == 288) {
            v = (l == 0) ? m2b[0] : hm2b[l-1];
        }
        sw[idx] = __half2half2(__float2half(v));
    }
    __syncthreads();

    int tid = blockIdx.x*256 + threadIdx.x;
    if (tid >= NE/4) return;
    int p0 = tid*4;

    int4 pk01 = *(const int4*)(g_epack + p0);
    int4 pk23 = *(const int4*)(g_epack + p0 + 2);
    int e[4] = {pk01.x, pk01.z, pk23.x, pk23.z};
    int d[4] = {pk01.y, pk01.w, pk23.y, pk23.w};

    // a2[p][i] = {feat_i of edge 2p, feat_i of edge 2p+1}
    __half2 a2[2][16];
    {
        float a[4][16];
        #pragma unroll
        for (int q = 0; q < 4; q++) {
            const float4* ap = (const float4*)(ea + e[q]*16);
            #pragma unroll
            for (int r = 0; r < 4; r++) {
                float4 v = ap[r];
                a[q][4*r+0]=v.x; a[q][4*r+1]=v.y; a[q][4*r+2]=v.z; a[q][4*r+3]=v.w;
            }
        }
        #pragma unroll
        for (int i = 0; i < 16; i++) {
            a2[0][i] = __floats2half2_rn(a[0][i], a[1][i]);
            a2[1][i] = __floats2half2_rn(a[2][i], a[3][i]);
        }
    }

    const __half2 zero2 = __float2half2_rn(0.0f);

    #pragma unroll 1
    for (int l = 0; l < NL; l++) {
        const __half2* W = &sw[l*LSTRIDE];
        __half2 b2v = W[288];
        __half2 z0 = b2v, z1 = b2v;
        #pragma unroll
        for (int j = 0; j < 16; j++) {
            const __half2* wc = &W[j*16];
            __half2 b1j = W[256+j];
            __half2 w2j = W[272+j];
            __half2 t0 = b1j, t1 = b1j;
            #pragma unroll
            for (int i = 0; i < 16; i++) {
                __half2 w = wc[i];
                t0 = __hfma2(a2[0][i], w, t0);
                t1 = __hfma2(a2[1][i], w, t1);
            }
            t0 = __hmax2(t0, zero2);
            t1 = __hmax2(t1, zero2);
            z0 = __hfma2(t0, w2j, z0);
            z1 = __hfma2(t1, w2j, z1);
        }
        float2 f0 = __half22float2(z0);
        float2 f1 = __half22float2(z1);
        float4 ewv;
        ewv.x = 1.0f / (1.0f + __expf(-f0.x));
        ewv.y = 1.0f / (1.0f + __expf(-f0.y));
        ewv.z = 1.0f / (1.0f + __expf(-f1.x));
        ewv.w = 1.0f / (1.0f + __expf(-f1.y));
        *(float4*)(g_ew + l*NE + p0) = ewv;
        atomicAdd(&g_deg[d[0]*16 + l], ewv.x);
        atomicAdd(&g_deg[d[1]*16 + l], ewv.y);
        atomicAdd(&g_deg[d[2]*16 + l], ewv.z);
        atomicAdd(&g_deg[d[3]*16 + l], ewv.w);
    }
}

__global__ void k_rsqrt() {
    int i = blockIdx.x*blockDim.x + threadIdx.x;
    if (i < NN*16) g_deg[i] = rsqrtf(g_deg[i]);   // deg >= 1 always
}

// scale ew by dis_src ONLY (dis_dst is factored into k_agg's final multiply)
__global__ void k_norm() {
    int p = blockIdx.x*256 + threadIdx.x;   // always < NE
    int s = g_csrc[p];
    float ds[16];
    const float4* sp = (const float4*)(g_deg + s*16);
    #pragma unroll
    for (int q = 0; q < 4; q++) {
        float4 v = sp[q]; ds[4*q]=v.x; ds[4*q+1]=v.y; ds[4*q+2]=v.z; ds[4*q+3]=v.w;
    }
    #pragma unroll
    for (int l = 0; l < NL; l++)
        g_ew[l*NE + p] *= ds[l];
}

// ---------------- fused BN+ReLU + tensor-core GEMM (wmma m16n16k16) ----------------
// block = 256 threads (8 warps), 128 rows; each warp: 16 rows x 64 cols
__global__ __launch_bounds__(256) void k_gemm(
    const float* __restrict__ A, const float* __restrict__ W,
    __half* __restrict__ H, int slot)     // slot < 0 : no BN
{
    __shared__ __align__(32) __half sA[128*64];   // 16 KB, fp16 BN-relu'd A tile
    __shared__ __align__(32) __half sW[64*64];    // 8 KB,  fp16 weights (k-major [k][n])
    __shared__ __align__(32) float  sC[8][16*64]; // 32 KB, per-warp fp32 C staging
    __shared__ float smu[64], ssc[64];

    int t = threadIdx.x;
    int base = blockIdx.x*128;

    if (slot >= 0 && t < 64) {
        double mu  = g_colsum[slot*64 + t] / (double)NN;
        double var = g_colsq[slot*64 + t] / (double)NN - mu*mu;
        if (var < 0.0) var = 0.0;
        smu[t] = (float)mu;
        ssc[t] = (float)(1.0 / sqrt(var + 1e-5));
    }
    // weights -> fp16 smem (no dependence on smu)
    {
        const float4* W4 = (const float4*)W;
        for (int i = t; i < 1024; i += 256) {
            float4 v = W4[i];
            __half2 h0 = __floats2half2_rn(v.x, v.y);
            __half2 h1 = __floats2half2_rn(v.z, v.w);
            uint2 u; u.x = *(unsigned*)&h0; u.y = *(unsigned*)&h1;
            *(uint2*)(sW + i*4) = u;
        }
    }
    __syncthreads();   // smu ready for A staging

    // stage A tile: BN+ReLU+fp16 via float4 loads (8 per thread)
    {
        const float4* A4 = (const float4*)A;
        const int maxi = ((NN - base < 128 ? NN - base : 128) * 64) >> 2;  // valid float4s
        for (int i = t; i < 2048; i += 256) {
            float4 v;
            if (i < maxi) v = A4[(size_t)base*16 + i];
            else { v.x = v.y = v.z = v.w = 0.0f; }
            if (slot >= 0) {
                int c = (i & 15)*4;
                v.x = fmaxf((v.x - smu[c+0]) * ssc[c+0], 0.0f);
                v.y = fmaxf((v.y - smu[c+1]) * ssc[c+1], 0.0f);
                v.z = fmaxf((v.z - smu[c+2]) * ssc[c+2], 0.0f);
                v.w = fmaxf((v.w - smu[c+3]) * ssc[c+3], 0.0f);
            }
            __half2 h0 = __floats2half2_rn(v.x, v.y);
            __half2 h1 = __floats2half2_rn(v.z, v.w);
            uint2 u; u.x = *(unsigned*)&h0; u.y = *(unsigned*)&h1;
            *(uint2*)(sA + i*4) = u;
        }
    }
    __syncthreads();

    int w = t >> 5;
    int lane = t & 31;

    wmma::fragment<wmma::accumulator, 16, 16, 16, float> acc[4];
    #pragma unroll
    for (int n = 0; n < 4; n++) wmma::fill_fragment(acc[n], 0.0f);

    #pragma unroll
    for (int k = 0; k < 4; k++) {
        wmma::fragment<wmma::matrix_a, 16, 16, 16, __half, wmma::row_major> af;
        wmma::load_matrix_sync(af, sA + (w*16)*64 + k*16, 64);
        #pragma unroll
        for (int n = 0; n < 4; n++) {
            wmma::fragment<wmma::matrix_b, 16, 16, 16, __half, wmma::row_major> bf;
            wmma::load_matrix_sync(bf, sW + (k*16)*64 + n*16, 64);
            wmma::mma_sync(acc[n], af, bf, acc[n]);
        }
    }

    // stage fp32 -> smem (per-warp private region), then fp16 coalesced store
    #pragma unroll
    for (int n = 0; n < 4; n++)
        wmma::store_matrix_sync(&sC[w][n*16], acc[n], 64, wmma::mem_row_major);

    int wrow = base + w*16;
    if (wrow < NN) {   // NN % 16 == 0, so warp tiles are all-or-nothing
        __half2* H2 = (__half2*)(H + (size_t)wrow*64);
        #pragma unroll
        for (int i = lane; i < 512; i += 32) {
            float x0 = sC[w][2*i], x1 = sC[w][2*i+1];
            H2[i] = __floats2half2_rn(x0, x1);
        }
    }
}

// ---------------- BN statistics (fp32 per-thread accumulation, fp64 reduce) ----------------
__global__ void k_bnstats(const float* __restrict__ A, int slot) {
    int t = threadIdx.x;
    int c = t & 63, rg = t >> 6;              // 256 threads: 4 row lanes x 64 cols
    float s = 0.0f, q = 0.0f;                 // ~49 elements per thread: fp32 is exact enough
    for (int r = blockIdx.x*4 + rg; r < NN; r += gridDim.x*4) {
        float v = A[r*64 + c];
        s += v; q = fmaf(v, v, q);
    }
    __shared__ float ss[256], sq[256];
    ss[t] = s; sq[t] = q; __syncthreads();
    if (t < 64) {
        double S = (double)ss[t] + (double)ss[t+64] + (double)ss[t+128] + (double)ss[t+192];
        double Q = (double)sq[t] + (double)sq[t+64] + (double)sq[t+128] + (double)sq[t+192];
        atomicAdd(&g_colsum[slot*64 + c], S);
        atomicAdd(&g_colsq [slot*64 + c], Q);
    }
}

// ---------------- CSR aggregation: LDG.128 gathers, 4 edges/warp-load ----------------
// lane = (edge slot 0-3)*8 + (col group 0-7); each lane covers 8 fp16 cols.
// weights in nrm are ew*dis_src; self term weight dv (seeded by eg==0 ONLY);
// final result = dv*sum + bias.
__global__ __launch_bounds__(256) void k_agg(
    const __half* __restrict__ h, const float* __restrict__ nrm,
    int layer, const float* __restrict__ bias,
    float* __restrict__ cur, float* __restrict__ acc,
    const int* __restrict__ batch, int mode)
{
    int t = threadIdx.x;
    int w = (blockIdx.x*256 + t) >> 5;
    int lane = t & 31;
    if (w >= NN) return;
    int eg = lane >> 3;          // edge slot 0..3
    int cg = lane & 7;           // col group 0..7
    int cbase = cg*8;

    float dv = g_deg[w*16 + layer];   // dis_dst

    float a[8] = {0,0,0,0,0,0,0,0};
    if (eg == 0) {   // self term seeded ONCE (reduction sums over the 4 edge slots)
        uint4 hv = *(const uint4*)(h + (size_t)w*64 + cbase);
        const __half2* hh = (const __half2*)&hv;
        #pragma unroll
        for (int i = 0; i < 4; i++) {
            float2 f = __half22float2(hh[i]);
            a[2*i]   = dv * f.x;
            a[2*i+1] = dv * f.y;
        }
    }

    int p0 = g_rowptr[w], p1 = g_rowptr[w+1];
    for (int p = p0; p < p1; p += 4) {
        int ei = p + eg;
        bool valid = (ei < p1);
        int eidx = valid ? ei : p;
        float wt = nrm[eidx];
        if (!valid) wt = 0.0f;
        int s = g_csrc[eidx];
        uint4 hv = *(const uint4*)(h + (size_t)s*64 + cbase);
        const __half2* hh = (const __half2*)&hv;
        #pragma unroll
        for (int i = 0; i < 4; i++) {
            float2 f = __half22float2(hh[i]);
            a[2*i]   = fmaf(wt, f.x, a[2*i]);
            a[2*i+1] = fmaf(wt, f.y, a[2*i+1]);
        }
    }

    // reduce across the 4 edge slots (lanes cg, cg+8, cg+16, cg+24)
    #pragma unroll
    for (int i = 0; i < 8; i++) {
        a[i] += __shfl_xor_sync(0xffffffffu, a[i], 8);
        a[i] += __shfl_xor_sync(0xffffffffu, a[i], 16);
    }

    if (lane < 8) {
        float4 b0 = *(const float4*)(bias + cbase);
        float4 b1 = *(const float4*)(bias + cbase + 4);
        float o[8];
        o[0] = fmaf(dv, a[0], b0.x); o[1] = fmaf(dv, a[1], b0.y);
        o[2] = fmaf(dv, a[2], b0.z); o[3] = fmaf(dv, a[3], b0.w);
        o[4] = fmaf(dv, a[4], b1.x); o[5] = fmaf(dv, a[5], b1.y);
        o[6] = fmaf(dv, a[6], b1.z); o[7] = fmaf(dv, a[7], b1.w);

        size_t off = (size_t)w*64 + cbase;
        if (mode & M_SKIP) {
            float4 s0 = *(float4*)(acc + off);
            float4 s1 = *(float4*)(acc + off + 4);
            o[0] += s0.x; o[1] += s0.y; o[2] += s0.z; o[3] += s0.w;
            o[4] += s1.x; o[5] += s1.y; o[6] += s1.z; o[7] += s1.w;
            s0.x += o[0]; s0.y += o[1]; s0.z += o[2]; s0.w += o[3];
            s1.x += o[4]; s1.y += o[5]; s1.z += o[6]; s1.w += o[7];
            *(float4*)(acc + off)     = s0;
            *(float4*)(acc + off + 4) = s1;
        }
        float4 c0, c1;
        c0.x=o[0]; c0.y=o[1]; c0.z=o[2]; c0.w=o[3];
        c1.x=o[4]; c1.y=o[5]; c1.z=o[6]; c1.w=o[7];
        *(float4*)(cur + off)     = c0;
        *(float4*)(cur + off + 4) = c1;
        if (mode & M_COPY) {
            *(float4*)(acc + off)     = c0;
            *(float4*)(acc + off + 4) = c1;
        }
        if (mode & M_POOL) {
            int b = batch[w];
            #pragma unroll
            for (int i = 0; i < 8; i++) {
                float rv = fmaxf(o[i], 0.0f);
                atomicMax((int*)&g_pool[b*64 + cbase + i], __float_as_int(rv));
            }
        }
    }
}

// ---------------- readout ----------------
__global__ void k_final(const float* __restrict__ linW, const float* __restrict__ linb,
                        float* __restrict__ out) {
    int g = blockIdx.x*blockDim.x + threadIdx.x;
    if (g >= NG) return;
    float a0 = linb[0], a1 = linb[1];
    #pragma unroll 8
    for (int c = 0; c < CC; c++) {
        float v = g_pool[g*64 + c];
        a0 = fmaf(v, linW[c*2+0], a0);
        a1 = fmaf(v, linW[c*2+1], a1);
    }
    out[g*2+0] = a0;
    out[g*2+1] = a1;
}

// ---------------- launch ----------------
extern "C" void kernel_launch(void* const* d_in, const int* in_sizes, int n_in,
                              void* d_out, int out_size)
{
    const float* x     = (const float*)d_in[0];
    const int*   ei    = (const int*)  d_in[1];
    const int*   batch = (const int*)  d_in[2];
    /* d_in[3] = dropout (unused, eval mode) */
    const float* ea    = (const float*)d_in[4];
    const float* Wlin1 = (const float*)d_in[5];
    const float* bias1 = (const float*)d_in[6];
    const float* m1W1  = (const float*)d_in[7];
    const float* m1b1  = (const float*)d_in[8];
    const float* m2W1  = (const float*)d_in[9];
    const float* m2b1  = (const float*)d_in[10];
    const float* hWlin = (const float*)d_in[11];
    const float* hbias = (const float*)d_in[12];
    const float* hm1W  = (const float*)d_in[13];
    const float* hm1b  = (const float*)d_in[14];
    const float* hm2W  = (const float*)d_in[15];
    const float* hm2b  = (const float*)d_in[16];
    const float* linW  = (const float*)d_in[17];
    const float* linb  = (const float*)d_in[18];
    float* out = (float*)d_out;

    const int* src = ei;
    const int* dst = ei + NE;

    __half *p_h;
    float *p_cur, *p_acc, *p_ew;
    cudaGetSymbolAddress((void**)&p_h,   g_h);
    cudaGetSymbolAddress((void**)&p_cur, g_cur);
    cudaGetSymbolAddress((void**)&p_acc, g_acc);
    cudaGetSymbolAddress((void**)&p_ew,  g_ew);

    const int EB = NE / 256;                  // 3125 (exact)
    const int MB = (NE/4 + 255) / 256;        // 782 (edgemlp, 4 edges/thread)
    const int GB = (NN + 127) / 128;          // 391 (gemm, 128 rows/block)
    const int AB = (NN*32) / 256;             // 6250 (exact)

    // prologue: CSR + all edge norms for all 13 layers
    k_reset  <<<(NN*16 + 255)/256, 256>>>();
    k_hist   <<<EB, 256>>>(dst);
    k_scanall<<<1, 1024>>>();
    k_scatter<<<EB, 256>>>(src, dst);
    k_edgemlp<<<MB, 256>>>(ea, m1W1, m1b1, m2W1, m2b1, hm1W, hm1b, hm2W, hm2b);
    k_rsqrt  <<<(NN*16 + 255)/256, 256>>>();
    k_norm   <<<EB, 256>>>();

    // conv1
    k_gemm<<<GB, 256>>>(x, Wlin1, p_h, -1);
    k_agg <<<AB, 256>>>(p_h, p_ew, 0, bias1, p_cur, p_acc, batch, M_COPY);

    // 12 hidden convs (6 blocks x 2)
    for (int j = 0; j < 12; j++) {
        int l = j + 1;
        k_bnstats<<<256, 256>>>(p_cur, j);
        k_gemm<<<GB, 256>>>(p_cur, hWlin + j*CC*CC, p_h, j);
        int mode;
        if (j == 11)      mode = M_SKIP | M_POOL;   // last: skip + relu + pool
        else if (j & 1)   mode = M_SKIP;            // end of block: dense skip
        else              mode = 0;
        k_agg <<<AB, 256>>>(p_h, p_ew + l*NE, l, hbias + j*CC, p_cur, p_acc, batch, mode);
    }

    k_final<<<(NG + 63)/64, 64>>>(linW, linb, out);
}